// round 12
// baseline (speedup 1.0000x reference)
#include <cuda_runtime.h>
#include <cuda_bf16.h>
#include <math.h>
#include <stdint.h>

#define BB 4
#define SS 2048
#define EE 1024
#define HH 16
#define DD 64
#define ROWS (BB*SS)          // 8192

#define NEG_INF (__int_as_float(0xff800000))

// ---------------- scratch (device globals: no runtime allocation) ----------
__device__ __align__(16) __nv_bfloat16 g_xh[ROWS*EE];
__device__ __align__(16) __nv_bfloat16 g_xl[ROWS*EE];
__device__ __align__(16) __nv_bfloat16 g_qkvh[3u*ROWS*EE];
__device__ __align__(16) __nv_bfloat16 g_qkvl[3u*ROWS*EE];
__device__ __align__(16) __nv_bfloat16 g_ah[ROWS*EE];
__device__ __align__(16) __nv_bfloat16 g_al[ROWS*EE];
__device__ __align__(16) __nv_bfloat16 g_wh[4u*EE*EE];
__device__ __align__(16) __nv_bfloat16 g_wl[4u*EE*EE];

#define N4X (ROWS*EE/4)
#define N4W (EE*EE/4)

// ---------------------------------------------------------------------------
// Fused fp32 -> bf16 hi/lo split for x + all 4 weights (single launch)
// ---------------------------------------------------------------------------
__global__ __launch_bounds__(256)
void split_all(const float4* __restrict__ x,
               const float4* __restrict__ w0, const float4* __restrict__ w1,
               const float4* __restrict__ w2, const float4* __restrict__ w3,
               uint2* __restrict__ xh, uint2* __restrict__ xl,
               uint2* __restrict__ wh, uint2* __restrict__ wl)
{
    int i = blockIdx.x * 256 + threadIdx.x;
    const float4* src; uint2 *dh, *dl;
    if (i < N4X) {
        src = x + i; dh = xh + i; dl = xl + i;
    } else {
        int j = i - N4X;
        int t = j >> 18;
        int loc = j & (N4W - 1);
        const float4* ws[4] = {w0, w1, w2, w3};
        src = ws[t] + loc;
        dh = wh + (size_t)t * N4W + loc;
        dl = wl + (size_t)t * N4W + loc;
    }
    float4 v = *src;
    float vv[4] = {v.x, v.y, v.z, v.w};
    unsigned hu[4], lu[4];
    #pragma unroll
    for (int j = 0; j < 4; ++j) {
        __nv_bfloat16 h = __float2bfloat16(vv[j]);
        float r = vv[j] - __bfloat162float(h);
        __nv_bfloat16 l = __float2bfloat16(r);
        hu[j] = (unsigned)__bfloat16_as_ushort(h);
        lu[j] = (unsigned)__bfloat16_as_ushort(l);
    }
    uint2 ho, lv;
    ho.x = hu[0] | (hu[1] << 16); ho.y = hu[2] | (hu[3] << 16);
    lv.x = lu[0] | (lu[1] << 16); lv.y = lu[2] | (lu[3] << 16);
    *dh = ho; *dl = lv;
}

// ---------------------------------------------------------------------------
// mma.sync helpers
// ---------------------------------------------------------------------------
__device__ __forceinline__ void cp16(uint32_t saddr, const void* gptr) {
    asm volatile("cp.async.cg.shared.global [%0], [%1], 16;"
                 :: "r"(saddr), "l"(gptr));
}
__device__ __forceinline__ void cp_commit() {
    asm volatile("cp.async.commit_group;" ::: "memory");
}
__device__ __forceinline__ void ldsm4(uint32_t* r, uint32_t addr) {
    asm volatile("ldmatrix.sync.aligned.m8n8.x4.shared.b16 {%0,%1,%2,%3}, [%4];"
                 : "=r"(r[0]), "=r"(r[1]), "=r"(r[2]), "=r"(r[3]) : "r"(addr));
}
__device__ __forceinline__ void ldsm4t(uint32_t* r, uint32_t addr) {
    asm volatile("ldmatrix.sync.aligned.m8n8.x4.trans.shared.b16 {%0,%1,%2,%3}, [%4];"
                 : "=r"(r[0]), "=r"(r[1]), "=r"(r[2]), "=r"(r[3]) : "r"(addr));
}
__device__ __forceinline__ void mma16816(float* c, const uint32_t* a, const uint32_t* b) {
    asm volatile(
        "mma.sync.aligned.m16n8k16.row.col.f32.bf16.bf16.f32 "
        "{%0,%1,%2,%3}, {%4,%5,%6,%7}, {%8,%9}, {%0,%1,%2,%3};"
        : "+f"(c[0]), "+f"(c[1]), "+f"(c[2]), "+f"(c[3])
        : "r"(a[0]), "r"(a[1]), "r"(a[2]), "r"(a[3]), "r"(b[0]), "r"(b[1]));
}
__device__ __forceinline__ void splitpack(float a, float b, uint32_t& hi, uint32_t& lo) {
    __nv_bfloat16 ha = __float2bfloat16(a), hb = __float2bfloat16(b);
    uint32_t hh = (uint32_t)__bfloat16_as_ushort(ha) |
                  ((uint32_t)__bfloat16_as_ushort(hb) << 16);
    __nv_bfloat16 la = __float2bfloat16(a - __bfloat162float(ha));
    __nv_bfloat16 lb = __float2bfloat16(b - __bfloat162float(hb));
    uint32_t ll = (uint32_t)__bfloat16_as_ushort(la) |
                  ((uint32_t)__bfloat16_as_ushort(lb) << 16);
    hi = hh; lo = ll;
}

// ===========================================================================
// GEMM core v4: CTA tile 128x128, 8 warps (4x2), warp tile 32x64, k-chunk 32,
// 3-stage cp.async pipeline with 64B rows + SW64 swizzle.
// 96 KB smem, <=128 regs  =>  2 CTAs/SM (4 warps/SMSP).
// ===========================================================================
#define GKC 32
#define GNKC (EE/GKC)        // 32 chunks
#define G4_AL 8192
#define G4_BH 16384
#define G4_BL 24576
#define G4_STAGE 32768

template<bool QKV>
__global__ __launch_bounds__(256, 2)
void mma_gemm(const __nv_bfloat16* __restrict__ Ah0, const __nv_bfloat16* __restrict__ Al0,
              const __nv_bfloat16* __restrict__ Wh0, const __nv_bfloat16* __restrict__ Wl0,
              const float* __restrict__ bias, float* __restrict__ C,
              __nv_bfloat16* __restrict__ Ch0, __nv_bfloat16* __restrict__ Cl0)
{
    extern __shared__ char smem[];
    const uint32_t sb = (uint32_t)__cvta_generic_to_shared(smem);
    const int K = EE, N = EE;

    const int tid = threadIdx.x;
    const int w = tid >> 5, lane = tid & 31;
    const int wm = w & 3, wn = w >> 2;               // 4 x 2 warp grid (32x64 tiles)
    const int wsel = QKV ? (blockIdx.x >> 3) : 0;
    const int bm = blockIdx.y * 128;
    const int bn = QKV ? ((blockIdx.x & 7) * 128) : (blockIdx.x * 128);

    const __nv_bfloat16* Ahp = Ah0 + (size_t)bm * K;
    const __nv_bfloat16* Alp = Al0 + (size_t)bm * K;
    const __nv_bfloat16* Bhp = Wh0 + (size_t)wsel * EE * EE + (size_t)bn * K;
    const __nv_bfloat16* Blp = Wl0 + (size_t)wsel * EE * EE + (size_t)bn * K;
    __nv_bfloat16* Ch = QKV ? (Ch0 + (size_t)wsel * ROWS * EE) : nullptr;
    __nv_bfloat16* Cl = QKV ? (Cl0 + (size_t)wsel * ROWS * EE) : nullptr;

    // ldmatrix geometry (64B rows; chunk = 16B col index 0..3, xor by (row>>1)&3)
    const int r8 = lane & 7, g = lane >> 3;
    const int arow = wm * 32 + r8 + (g & 1) * 8;     // + mf*16 (xor invariant)
    const int achk = g >> 1;                          // + ks*2
    const uint32_t axor = (uint32_t)((arow >> 1) & 3);
    const int brow = wn * 64 + r8 + (g >> 1) * 8;    // + nf2*16
    const int bchk = g & 1;                           // + ks*2
    const uint32_t bxor = (uint32_t)((brow >> 1) & 3);

    float acc[2][8][4];
    #pragma unroll
    for (int a = 0; a < 2; ++a)
        #pragma unroll
        for (int b = 0; b < 8; ++b)
            #pragma unroll
            for (int c = 0; c < 4; ++c) acc[a][b][c] = 0.f;

    // stage loader: 2048 16B segs (Ah 512 | Al 512 | Bh 512 | Bl 512),
    // 8 per thread. seg: row (0..127), c (0..3).
    const int lrow = tid >> 1;               // 0..127
    const int lc0 = (tid & 1) * 2;           // 0 or 2 (two consecutive chunks)
    const uint32_t lxor = (uint32_t)((lrow >> 1) & 3);
    auto load_stage = [&](int slot, int kc) {
        const uint32_t sbase = sb + (uint32_t)(slot * G4_STAGE);
        const uint32_t rbase = sbase + (uint32_t)(lrow * 64);
        const size_t goff = (size_t)lrow * K + kc * GKC;
        #pragma unroll
        for (int cc = 0; cc < 2; ++cc) {
            const int c = lc0 + cc;
            const uint32_t so = (uint32_t)(((uint32_t)c ^ lxor) << 4);
            cp16(rbase + so,           Ahp + goff + c * 8);
            cp16(rbase + so + G4_AL,   Alp + goff + c * 8);
            cp16(rbase + so + G4_BH,   Bhp + goff + c * 8);
            cp16(rbase + so + G4_BL,   Blp + goff + c * 8);
        }
        cp_commit();
    };

    load_stage(0, 0);
    load_stage(1, 1);

    int slot = 2, cslot = 0;
    for (int kc = 0; kc < GNKC; ++kc) {
        asm volatile("cp.async.wait_group 1;" ::: "memory");
        __syncthreads();

        if (kc + 2 < GNKC) {
            load_stage(slot, kc + 2);
        } else {
            cp_commit();                     // keep group accounting consistent
        }
        if (++slot == 3) slot = 0;

        const uint32_t stg = sb + (uint32_t)(cslot * G4_STAGE);
        if (++cslot == 3) cslot = 0;

        #pragma unroll
        for (int ks = 0; ks < 2; ++ks) {
            uint32_t aH[2][4], aL[2][4];
            #pragma unroll
            for (int mf = 0; mf < 2; ++mf) {
                const uint32_t ro = stg + (uint32_t)((arow + mf * 16) * 64)
                                  + (((uint32_t)(ks * 2 + achk) ^ axor) << 4);
                ldsm4(aH[mf], ro);
                ldsm4(aL[mf], ro + G4_AL);
            }
            #pragma unroll
            for (int nf2 = 0; nf2 < 4; ++nf2) {
                uint32_t bH[4], bL[4];
                const uint32_t ro = stg + G4_BH + (uint32_t)((brow + nf2 * 16) * 64)
                                  + (((uint32_t)(ks * 2 + bchk) ^ bxor) << 4);
                ldsm4(bH, ro);
                ldsm4(bL, ro + G4_AL);       // Bl = Bh + 8192
                #pragma unroll
                for (int mf = 0; mf < 2; ++mf)
                    #pragma unroll
                    for (int j = 0; j < 2; ++j) {
                        float* c = acc[mf][nf2 * 2 + j];
                        mma16816(c, aH[mf], &bH[j * 2]);
                        mma16816(c, aH[mf], &bL[j * 2]);
                        mma16816(c, aL[mf], &bH[j * 2]);
                    }
            }
        }
    }

    const int row0 = bm + wm * 32 + (lane >> 2);
    const int col0 = bn + wn * 64 + (lane & 3) * 2;
    #pragma unroll
    for (int mf = 0; mf < 2; ++mf)
        #pragma unroll
        for (int nf = 0; nf < 8; ++nf) {
            const int r = row0 + mf * 16;
            const int col = col0 + nf * 8;
            if (QKV) {
                uint32_t h0, l0, h1, l1;
                splitpack(acc[mf][nf][0], acc[mf][nf][1], h0, l0);
                splitpack(acc[mf][nf][2], acc[mf][nf][3], h1, l1);
                *(uint32_t*)&Ch[(size_t)r * N + col]       = h0;
                *(uint32_t*)&Cl[(size_t)r * N + col]       = l0;
                *(uint32_t*)&Ch[(size_t)(r + 8) * N + col] = h1;
                *(uint32_t*)&Cl[(size_t)(r + 8) * N + col] = l1;
            } else {
                float b0 = bias[col], b1 = bias[col + 1];
                float2 v0, v1;
                v0.x = acc[mf][nf][0] + b0; v0.y = acc[mf][nf][1] + b1;
                v1.x = acc[mf][nf][2] + b0; v1.y = acc[mf][nf][3] + b1;
                *(float2*)&C[(size_t)r * N + col]       = v0;
                *(float2*)&C[(size_t)(r + 8) * N + col] = v1;
            }
        }
}

// ---------------------------------------------------------------------------
// Tensor-core causal flash attention (round-10 best version, unchanged).
// CTA: 256 q rows, 512 threads, triple-buffered KV, one sync per chunk.
// ---------------------------------------------------------------------------
#define FKVB 32768

__global__ __launch_bounds__(512, 1)
void flash_mma(const __nv_bfloat16* __restrict__ Qh, const __nv_bfloat16* __restrict__ Ql,
               const __nv_bfloat16* __restrict__ Kh, const __nv_bfloat16* __restrict__ Kl,
               const __nv_bfloat16* __restrict__ Vh, const __nv_bfloat16* __restrict__ Vl,
               __nv_bfloat16* __restrict__ Oh, __nv_bfloat16* __restrict__ Ol)
{
    extern __shared__ char smem[];
    const uint32_t sb = (uint32_t)__cvta_generic_to_shared(smem);
    const int tid = threadIdx.x, w = tid >> 5, lane = tid & 31;
    const int qt = (int)(gridDim.x - 1 - blockIdx.x);
    const int bh = blockIdx.y, b = bh >> 4, h = bh & 15;
    const size_t gbase = (size_t)(b * SS) * EE + h * 64;

    const __nv_bfloat16* kv[4] = { Kh, Kl, Vh, Vl };

    auto load_kv = [&](int chunk) {
        const uint32_t bufb = sb + 65536 + (uint32_t)((chunk % 3) * FKVB);
        #pragma unroll
        for (int i = 0; i < 4; ++i) {
            int idx = tid + i * 512;
            int t = idx >> 9, rr = (idx & 511) >> 3, s8 = idx & 7;
            cp16(bufb + t * 8192 + rr * 128 + (uint32_t)((s8 * 16) ^ ((rr & 7) << 4)),
                 kv[t] + gbase + (size_t)(chunk * 64 + rr) * EE + s8 * 8);
        }
    };

    #pragma unroll
    for (int i = 0; i < 8; ++i) {
        int idx = tid + i * 512;
        int t = idx >> 11, rr = (idx & 2047) >> 3, s8 = idx & 7;
        const __nv_bfloat16* src = (t ? Ql : Qh) + gbase + (size_t)(qt * 256 + rr) * EE + s8 * 8;
        cp16(sb + t * 32768 + rr * 128 + (uint32_t)((s8 * 16) ^ ((rr & 7) << 4)), src);
    }
    load_kv(0);
    cp_commit();
    load_kv(1);
    cp_commit();

    const int r8 = lane & 7, g = lane >> 3;
    const int arow = w * 16 + r8 + (g & 1) * 8;
    const uint32_t axor = (uint32_t)((arow & 7) << 4);
    const int acolg = (g >> 1) * 16;
    const int brow = r8 + (g >> 1) * 8;
    const uint32_t bxor = (uint32_t)((brow & 7) << 4);
    const int bcolg = (g & 1) * 16;
    const int vrow = r8 + (g & 1) * 8;
    const uint32_t vxor = (uint32_t)((vrow & 7) << 4);
    const int vcolg = (g >> 1) * 16;

    float oacc[8][4];
    #pragma unroll
    for (int j = 0; j < 8; ++j)
        #pragma unroll
        for (int e = 0; e < 4; ++e) oacc[j][e] = 0.f;
    float m0 = NEG_INF, m1 = NEG_INF, l0 = 0.f, l1 = 0.f;

    const int nch = 4 * qt + 4;
    const int wminrow = qt * 256 + w * 16;

    for (int c = 0; c < nch; ++c) {
        asm volatile("cp.async.wait_group 1;" ::: "memory");
        __syncthreads();

        if (c + 2 < nch) load_kv(c + 2);
        cp_commit();

        if (c * 64 <= wminrow + 15) {
            const uint32_t bufb = sb + 65536 + (uint32_t)((c % 3) * FKVB);
            float sacc[8][4];
            #pragma unroll
            for (int j = 0; j < 8; ++j)
                #pragma unroll
                for (int e = 0; e < 4; ++e) sacc[j][e] = 0.f;

            #pragma unroll
            for (int ks = 0; ks < 4; ++ks) {
                uint32_t aH[4], aL[4];
                const uint32_t ao = (uint32_t)(arow * 128) + ((uint32_t)(ks * 32 + acolg) ^ axor);
                ldsm4(aH, sb + ao);
                ldsm4(aL, sb + 32768 + ao);
                const uint32_t colB = (uint32_t)(ks * 32 + bcolg) ^ bxor;
                #pragma unroll
                for (int nf2 = 0; nf2 < 4; ++nf2) {
                    uint32_t bH[4], bL[4];
                    const uint32_t ro = (uint32_t)((brow + nf2 * 16) * 128) + colB;
                    ldsm4(bH, bufb + ro);
                    ldsm4(bL, bufb + 8192 + ro);
                    #pragma unroll
                    for (int j = 0; j < 2; ++j) {
                        float* cc = sacc[nf2 * 2 + j];
                        mma16816(cc, aH, &bH[j * 2]);
                        mma16816(cc, aH, &bL[j * 2]);
                        mma16816(cc, aL, &bH[j * 2]);
                    }
                }
            }

            const int row0 = wminrow + (lane >> 2);
            if (c * 64 + 63 > wminrow) {
                #pragma unroll
                for (int j = 0; j < 8; ++j) {
                    int col = c * 64 + j * 8 + (lane & 3) * 2;
                    if (col     > row0)     sacc[j][0] = NEG_INF;
                    if (col + 1 > row0)     sacc[j][1] = NEG_INF;
                    if (col     > row0 + 8) sacc[j][2] = NEG_INF;
                    if (col + 1 > row0 + 8) sacc[j][3] = NEG_INF;
                }
            }
            float t0 = NEG_INF, t1 = NEG_INF;
            #pragma unroll
            for (int j = 0; j < 8; ++j) {
                sacc[j][0] *= 0.125f; sacc[j][1] *= 0.125f;
                sacc[j][2] *= 0.125f; sacc[j][3] *= 0.125f;
                t0 = fmaxf(t0, fmaxf(sacc[j][0], sacc[j][1]));
                t1 = fmaxf(t1, fmaxf(sacc[j][2], sacc[j][3]));
            }
            t0 = fmaxf(t0, __shfl_xor_sync(0xffffffffu, t0, 1));
            t0 = fmaxf(t0, __shfl_xor_sync(0xffffffffu, t0, 2));
            t1 = fmaxf(t1, __shfl_xor_sync(0xffffffffu, t1, 1));
            t1 = fmaxf(t1, __shfl_xor_sync(0xffffffffu, t1, 2));

            const float mn0 = fmaxf(m0, t0), mn1 = fmaxf(m1, t1);
            const float cr0 = __expf(m0 - mn0), cr1 = __expf(m1 - mn1);
            float s0 = 0.f, s1 = 0.f;
            #pragma unroll
            for (int j = 0; j < 8; ++j) {
                float p0 = __expf(sacc[j][0] - mn0); sacc[j][0] = p0; s0 += p0;
                float p1 = __expf(sacc[j][1] - mn0); sacc[j][1] = p1; s0 += p1;
                float p2 = __expf(sacc[j][2] - mn1); sacc[j][2] = p2; s1 += p2;
                float p3 = __expf(sacc[j][3] - mn1); sacc[j][3] = p3; s1 += p3;
            }
            s0 += __shfl_xor_sync(0xffffffffu, s0, 1);
            s0 += __shfl_xor_sync(0xffffffffu, s0, 2);
            s1 += __shfl_xor_sync(0xffffffffu, s1, 1);
            s1 += __shfl_xor_sync(0xffffffffu, s1, 2);
            l0 = l0 * cr0 + s0; l1 = l1 * cr1 + s1;
            m0 = mn0; m1 = mn1;
            #pragma unroll
            for (int j = 0; j < 8; ++j) {
                oacc[j][0] *= cr0; oacc[j][1] *= cr0;
                oacc[j][2] *= cr1; oacc[j][3] *= cr1;
            }

            #pragma unroll
            for (int ks = 0; ks < 4; ++ks) {
                uint32_t aPh[4], aPl[4];
                splitpack(sacc[2*ks][0],   sacc[2*ks][1],   aPh[0], aPl[0]);
                splitpack(sacc[2*ks][2],   sacc[2*ks][3],   aPh[1], aPl[1]);
                splitpack(sacc[2*ks+1][0], sacc[2*ks+1][1], aPh[2], aPl[2]);
                splitpack(sacc[2*ks+1][2], sacc[2*ks+1][3], aPh[3], aPl[3]);
                const uint32_t rbase = (uint32_t)((ks * 16 + vrow) * 128);
                #pragma unroll
                for (int nf2 = 0; nf2 < 4; ++nf2) {
                    uint32_t vH[4], vL[4];
                    const uint32_t vo = rbase + ((uint32_t)(nf2 * 32 + vcolg) ^ vxor);
                    ldsm4t(vH, bufb + 16384 + vo);
                    ldsm4t(vL, bufb + 24576 + vo);
                    #pragma unroll
                    for (int j = 0; j < 2; ++j) {
                        float* cc = oacc[nf2 * 2 + j];
                        mma16816(cc, aPh, &vH[j * 2]);
                        mma16816(cc, aPh, &vL[j * 2]);
                        mma16816(cc, aPl, &vH[j * 2]);
                    }
                }
            }
        }
    }

    const float inv0 = 1.f / l0, inv1 = 1.f / l1;
    const int orow = qt * 256 + w * 16 + (lane >> 2);
    const int ocol = (lane & 3) * 2;
    #pragma unroll
    for (int j = 0; j < 8; ++j) {
        uint32_t h0, lo0, h1, lo1;
        splitpack(oacc[j][0] * inv0, oacc[j][1] * inv0, h0, lo0);
        splitpack(oacc[j][2] * inv1, oacc[j][3] * inv1, h1, lo1);
        size_t a0 = gbase + (size_t)orow * EE + j * 8 + ocol;
        size_t a1 = a0 + (size_t)8 * EE;
        *(uint32_t*)&Oh[a0] = h0; *(uint32_t*)&Ol[a0] = lo0;
        *(uint32_t*)&Oh[a1] = h1; *(uint32_t*)&Ol[a1] = lo1;
    }
}

// ---------------------------------------------------------------------------
extern "C" void kernel_launch(void* const* d_in, const int* in_sizes, int n_in,
                              void* d_out, int out_size)
{
    const float* x   = (const float*)d_in[0];
    const float* w_q = (const float*)d_in[2];
    const float* w_k = (const float*)d_in[3];
    const float* w_v = (const float*)d_in[4];
    const float* w_o = (const float*)d_in[5];
    const float* b_o = (const float*)d_in[6];
    float* out = (float*)d_out;

    __nv_bfloat16 *xh, *xl, *qkvh, *qkvl, *ah, *al, *wh, *wl;
    cudaGetSymbolAddress((void**)&xh,   g_xh);
    cudaGetSymbolAddress((void**)&xl,   g_xl);
    cudaGetSymbolAddress((void**)&qkvh, g_qkvh);
    cudaGetSymbolAddress((void**)&qkvl, g_qkvl);
    cudaGetSymbolAddress((void**)&ah,   g_ah);
    cudaGetSymbolAddress((void**)&al,   g_al);
    cudaGetSymbolAddress((void**)&wh,   g_wh);
    cudaGetSymbolAddress((void**)&wl,   g_wl);

    const int nblk = (N4X + 4 * N4W) / 256;
    split_all<<<nblk, 256>>>((const float4*)x,
                             (const float4*)w_q, (const float4*)w_k,
                             (const float4*)w_v, (const float4*)w_o,
                             (uint2*)xh, (uint2*)xl, (uint2*)wh, (uint2*)wl);

    const int gsmem = 3 * G4_STAGE;      // 98304 (2 CTAs/SM)
    cudaFuncSetAttribute(mma_gemm<true>,  cudaFuncAttributeMaxDynamicSharedMemorySize, gsmem);
    cudaFuncSetAttribute(mma_gemm<false>, cudaFuncAttributeMaxDynamicSharedMemorySize, gsmem);
    dim3 gq(3 * EE / 128, ROWS / 128);   // (24, 64)
    mma_gemm<true><<<gq, 256, gsmem>>>(xh, xl, wh, wl, nullptr, nullptr, qkvh, qkvl);

    const size_t TS = (size_t)ROWS * EE;
    const int fsmem = 65536 + 3 * FKVB;  // 163840
    cudaFuncSetAttribute(flash_mma, cudaFuncAttributeMaxDynamicSharedMemorySize, fsmem);
    dim3 fgrid(SS / 256, BB * HH);
    flash_mma<<<fgrid, 512, fsmem>>>(qkvh, qkvl, qkvh + TS, qkvl + TS,
                                     qkvh + 2 * TS, qkvl + 2 * TS, ah, al);

    dim3 gg(EE / 128, ROWS / 128);       // (8, 64)
    mma_gemm<false><<<gg, 256, gsmem>>>(ah, al, wh + 3ull*EE*EE, wl + 3ull*EE*EE,
                                        b_o, out, nullptr, nullptr);
}

// round 13
// speedup vs baseline: 1.1953x; 1.1953x over previous
#include <cuda_runtime.h>
#include <cuda_bf16.h>
#include <cuda_fp16.h>
#include <math.h>
#include <stdint.h>

#define BB 4
#define SS 2048
#define EE 1024
#define HH 16
#define DD 64
#define ROWS (BB*SS)          // 8192

#define NEG_INF (__int_as_float(0xff800000))
#define QSCALE 0.18033688011112042f   // 0.125 * log2(e)

// ---------------- scratch (device globals: no runtime allocation) ----------
__device__ __align__(16) __nv_bfloat16 g_xh[ROWS*EE];
__device__ __align__(16) __nv_bfloat16 g_xl[ROWS*EE];
__device__ __align__(16) __nv_bfloat16 g_qkvh[3u*ROWS*EE];   // V slice holds fp16
__device__ __align__(16) __nv_bfloat16 g_qkvl[3u*ROWS*EE];
__device__ __align__(16) __nv_bfloat16 g_ah[ROWS*EE];
__device__ __align__(16) __nv_bfloat16 g_al[ROWS*EE];
__device__ __align__(16) __nv_bfloat16 g_wh[4u*EE*EE];
__device__ __align__(16) __nv_bfloat16 g_wl[4u*EE*EE];

#define N4X (ROWS*EE/4)
#define N4W (EE*EE/4)

// ---------------------------------------------------------------------------
// Fused fp32 -> bf16 hi/lo split for x + all 4 weights (single launch)
// ---------------------------------------------------------------------------
__global__ __launch_bounds__(256)
void split_all(const float4* __restrict__ x,
               const float4* __restrict__ w0, const float4* __restrict__ w1,
               const float4* __restrict__ w2, const float4* __restrict__ w3,
               uint2* __restrict__ xh, uint2* __restrict__ xl,
               uint2* __restrict__ wh, uint2* __restrict__ wl)
{
    int i = blockIdx.x * 256 + threadIdx.x;
    const float4* src; uint2 *dh, *dl;
    if (i < N4X) {
        src = x + i; dh = xh + i; dl = xl + i;
    } else {
        int j = i - N4X;
        int t = j >> 18;
        int loc = j & (N4W - 1);
        const float4* ws[4] = {w0, w1, w2, w3};
        src = ws[t] + loc;
        dh = wh + (size_t)t * N4W + loc;
        dl = wl + (size_t)t * N4W + loc;
    }
    float4 v = *src;
    float vv[4] = {v.x, v.y, v.z, v.w};
    unsigned hu[4], lu[4];
    #pragma unroll
    for (int j = 0; j < 4; ++j) {
        __nv_bfloat16 h = __float2bfloat16(vv[j]);
        float r = vv[j] - __bfloat162float(h);
        __nv_bfloat16 l = __float2bfloat16(r);
        hu[j] = (unsigned)__bfloat16_as_ushort(h);
        lu[j] = (unsigned)__bfloat16_as_ushort(l);
    }
    uint2 ho, lv;
    ho.x = hu[0] | (hu[1] << 16); ho.y = hu[2] | (hu[3] << 16);
    lv.x = lu[0] | (lu[1] << 16); lv.y = lu[2] | (lu[3] << 16);
    *dh = ho; *dl = lv;
}

// ---------------------------------------------------------------------------
// mma.sync helpers
// ---------------------------------------------------------------------------
__device__ __forceinline__ void cp16(uint32_t saddr, const void* gptr) {
    asm volatile("cp.async.cg.shared.global [%0], [%1], 16;"
                 :: "r"(saddr), "l"(gptr));
}
__device__ __forceinline__ void cp_commit() {
    asm volatile("cp.async.commit_group;" ::: "memory");
}
__device__ __forceinline__ void ldsm4(uint32_t* r, uint32_t addr) {
    asm volatile("ldmatrix.sync.aligned.m8n8.x4.shared.b16 {%0,%1,%2,%3}, [%4];"
                 : "=r"(r[0]), "=r"(r[1]), "=r"(r[2]), "=r"(r[3]) : "r"(addr));
}
__device__ __forceinline__ void ldsm4t(uint32_t* r, uint32_t addr) {
    asm volatile("ldmatrix.sync.aligned.m8n8.x4.trans.shared.b16 {%0,%1,%2,%3}, [%4];"
                 : "=r"(r[0]), "=r"(r[1]), "=r"(r[2]), "=r"(r[3]) : "r"(addr));
}
__device__ __forceinline__ void mma16816(float* c, const uint32_t* a, const uint32_t* b) {
    asm volatile(
        "mma.sync.aligned.m16n8k16.row.col.f32.bf16.bf16.f32 "
        "{%0,%1,%2,%3}, {%4,%5,%6,%7}, {%8,%9}, {%0,%1,%2,%3};"
        : "+f"(c[0]), "+f"(c[1]), "+f"(c[2]), "+f"(c[3])
        : "r"(a[0]), "r"(a[1]), "r"(a[2]), "r"(a[3]), "r"(b[0]), "r"(b[1]));
}
__device__ __forceinline__ void mma16816h(float* c, const uint32_t* a, const uint32_t* b) {
    asm volatile(
        "mma.sync.aligned.m16n8k16.row.col.f32.f16.f16.f32 "
        "{%0,%1,%2,%3}, {%4,%5,%6,%7}, {%8,%9}, {%0,%1,%2,%3};"
        : "+f"(c[0]), "+f"(c[1]), "+f"(c[2]), "+f"(c[3])
        : "r"(a[0]), "r"(a[1]), "r"(a[2]), "r"(a[3]), "r"(b[0]), "r"(b[1]));
}
__device__ __forceinline__ void splitpack(float a, float b, uint32_t& hi, uint32_t& lo) {
    __nv_bfloat16 ha = __float2bfloat16(a), hb = __float2bfloat16(b);
    uint32_t hh = (uint32_t)__bfloat16_as_ushort(ha) |
                  ((uint32_t)__bfloat16_as_ushort(hb) << 16);
    __nv_bfloat16 la = __float2bfloat16(a - __bfloat162float(ha));
    __nv_bfloat16 lb = __float2bfloat16(b - __bfloat162float(hb));
    uint32_t ll = (uint32_t)__bfloat16_as_ushort(la) |
                  ((uint32_t)__bfloat16_as_ushort(lb) << 16);
    hi = hh; lo = ll;
}
__device__ __forceinline__ void splitpackh(float a, float b, uint32_t& hi, uint32_t& lo) {
    __half ha = __float2half_rn(a), hb = __float2half_rn(b);
    uint32_t hh = (uint32_t)__half_as_ushort(ha) |
                  ((uint32_t)__half_as_ushort(hb) << 16);
    __half la = __float2half_rn(a - __half2float(ha));
    __half lb = __float2half_rn(b - __half2float(hb));
    uint32_t ll = (uint32_t)__half_as_ushort(la) |
                  ((uint32_t)__half_as_ushort(lb) << 16);
    hi = hh; lo = ll;
}
// pack two fp32 -> f16x2 (a -> low half, b -> high half)
__device__ __forceinline__ uint32_t packh2(float a, float b) {
    uint32_t r;
    asm("cvt.rn.f16x2.f32 %0, %1, %2;" : "=r"(r) : "f"(b), "f"(a));
    return r;
}

#define NKC (EE/64)

// ===========================================================================
// GEMM core (round-10 best shape): CTA tile 128x256, 8 warps (2x4), warp tile
// 64x64, 2-stage cp.async double buffer (96 KB/stage).
// QKV epilogue: wsel 0 (Q) scaled by QSCALE, bf16 hi/lo; wsel 1 (K) bf16;
// wsel 2 (V) fp16 hi/lo.
// ===========================================================================
#define OF_AL 16384
#define OF_BH 32768
#define OF_BL 65536
#define GSTAGE 98304

template<bool QKV>
__global__ __launch_bounds__(256, 1)
void mma_gemm(const __nv_bfloat16* __restrict__ Ah0, const __nv_bfloat16* __restrict__ Al0,
              const __nv_bfloat16* __restrict__ Wh0, const __nv_bfloat16* __restrict__ Wl0,
              const float* __restrict__ bias, float* __restrict__ C,
              __nv_bfloat16* __restrict__ Ch0, __nv_bfloat16* __restrict__ Cl0)
{
    extern __shared__ char smem[];
    const uint32_t sb = (uint32_t)__cvta_generic_to_shared(smem);
    const int K = EE, N = EE;

    const int tid = threadIdx.x;
    const int w = tid >> 5, lane = tid & 31;
    const int wm = w & 1, wn = w >> 1;
    const int wsel = QKV ? (blockIdx.x >> 2) : 0;
    const int bm = blockIdx.y * 128;
    const int bn = QKV ? ((blockIdx.x & 3) * 256) : (blockIdx.x * 256);

    const __nv_bfloat16* Ahp = Ah0 + (size_t)bm * K;
    const __nv_bfloat16* Alp = Al0 + (size_t)bm * K;
    const __nv_bfloat16* Bhp = Wh0 + (size_t)wsel * EE * EE + (size_t)bn * K;
    const __nv_bfloat16* Blp = Wl0 + (size_t)wsel * EE * EE + (size_t)bn * K;
    __nv_bfloat16* Ch = QKV ? (Ch0 + (size_t)wsel * ROWS * EE) : nullptr;
    __nv_bfloat16* Cl = QKV ? (Cl0 + (size_t)wsel * ROWS * EE) : nullptr;

    const int r8 = lane & 7, g = lane >> 3;
    const int arow = wm * 64 + r8 + (g & 1) * 8;
    const int acolg = (g >> 1) * 16;
    const uint32_t axor = (uint32_t)((arow & 7) << 4);
    const int brow = wn * 64 + r8 + (g >> 1) * 8;
    const int bcolg = (g & 1) * 16;
    const uint32_t bxor = (uint32_t)((brow & 7) << 4);

    float acc[4][8][4];
    #pragma unroll
    for (int a = 0; a < 4; ++a)
        #pragma unroll
        for (int b = 0; b < 8; ++b)
            #pragma unroll
            for (int c = 0; c < 4; ++c) acc[a][b][c] = 0.f;

    auto load_stage = [&](int slot, int kc) {
        const uint32_t sbase = sb + (uint32_t)(slot * GSTAGE);
        #pragma unroll
        for (int i = 0; i < 24; ++i) {
            int idx = tid + i * 256;
            const __nv_bfloat16* src;
            uint32_t toff; int local;
            if (i < 4)       { local = idx;        src = Ahp; toff = 0; }
            else if (i < 8)  { local = idx - 1024; src = Alp; toff = OF_AL; }
            else if (i < 16) { local = idx - 2048; src = Bhp; toff = OF_BH; }
            else             { local = idx - 4096; src = Blp; toff = OF_BL; }
            int row = local >> 3, s8 = local & 7;
            cp16(sbase + toff + (uint32_t)(row * 128 + ((s8 * 16) ^ ((row & 7) << 4))),
                 src + (size_t)row * K + kc * 64 + s8 * 8);
        }
        cp_commit();
    };

    load_stage(0, 0);

    for (int kc = 0; kc < NKC; ++kc) {
        if (kc + 1 < NKC) {
            load_stage((kc + 1) & 1, kc + 1);
            asm volatile("cp.async.wait_group 1;" ::: "memory");
        } else {
            asm volatile("cp.async.wait_group 0;" ::: "memory");
        }
        __syncthreads();

        const uint32_t stg = sb + (uint32_t)((kc & 1) * GSTAGE);

        #pragma unroll
        for (int ks = 0; ks < 4; ++ks) {
            uint32_t aH[4][4], aL[4][4];
            const uint32_t colA = (uint32_t)(ks * 32 + acolg) ^ axor;
            const uint32_t colB = (uint32_t)(ks * 32 + bcolg) ^ bxor;
            #pragma unroll
            for (int mf = 0; mf < 4; ++mf) {
                const uint32_t ro = (uint32_t)((arow + mf * 16) * 128) + colA;
                ldsm4(aH[mf], stg + ro);
                ldsm4(aL[mf], stg + OF_AL + ro);
            }
            #pragma unroll
            for (int nf2 = 0; nf2 < 4; ++nf2) {
                uint32_t bH[4], bL[4];
                const uint32_t ro = (uint32_t)((brow + nf2 * 16) * 128) + colB;
                ldsm4(bH, stg + OF_BH + ro);
                ldsm4(bL, stg + OF_BL + ro);
                #pragma unroll
                for (int mf = 0; mf < 4; ++mf)
                    #pragma unroll
                    for (int j = 0; j < 2; ++j) {
                        float* c = acc[mf][nf2 * 2 + j];
                        mma16816(c, aH[mf], &bH[j * 2]);
                        mma16816(c, aH[mf], &bL[j * 2]);
                        mma16816(c, aL[mf], &bH[j * 2]);
                    }
            }
        }
        __syncthreads();
    }

    const int row0 = bm + wm * 64 + (lane >> 2);
    const int col0 = bn + wn * 64 + (lane & 3) * 2;
    const float esc = (QKV && wsel == 0) ? QSCALE : 1.0f;
    #pragma unroll
    for (int mf = 0; mf < 4; ++mf)
        #pragma unroll
        for (int nf = 0; nf < 8; ++nf) {
            const int r = row0 + mf * 16;
            const int col = col0 + nf * 8;
            if (QKV) {
                float f0 = acc[mf][nf][0] * esc, f1 = acc[mf][nf][1] * esc;
                float f2 = acc[mf][nf][2] * esc, f3 = acc[mf][nf][3] * esc;
                uint32_t h0, l0, h1, l1;
                if (wsel == 2) {          // V: fp16 hi/lo
                    splitpackh(f0, f1, h0, l0);
                    splitpackh(f2, f3, h1, l1);
                } else {                  // Q (scaled) / K: bf16 hi/lo
                    splitpack(f0, f1, h0, l0);
                    splitpack(f2, f3, h1, l1);
                }
                *(uint32_t*)&Ch[(size_t)r * N + col]       = h0;
                *(uint32_t*)&Cl[(size_t)r * N + col]       = l0;
                *(uint32_t*)&Ch[(size_t)(r + 8) * N + col] = h1;
                *(uint32_t*)&Cl[(size_t)(r + 8) * N + col] = l1;
            } else {
                float b0 = bias[col], b1 = bias[col + 1];
                float2 v0, v1;
                v0.x = acc[mf][nf][0] + b0; v0.y = acc[mf][nf][1] + b1;
                v1.x = acc[mf][nf][2] + b0; v1.y = acc[mf][nf][3] + b1;
                *(float2*)&C[(size_t)r * N + col]       = v0;
                *(float2*)&C[(size_t)(r + 8) * N + col] = v1;
            }
        }
}

// ---------------------------------------------------------------------------
// Tensor-core causal flash attention. Q pre-scaled by 0.125*log2(e) -> exp2.
// QK^T: bf16x3. PV: P as single fp16 (no split), V as fp16 hi/lo, 2 terms.
// CTA: 256 q rows, 512 threads, triple-buffered KV, one sync per chunk.
// ---------------------------------------------------------------------------
#define FKVB 32768

__global__ __launch_bounds__(512, 1)
void flash_mma(const __nv_bfloat16* __restrict__ Qh, const __nv_bfloat16* __restrict__ Ql,
               const __nv_bfloat16* __restrict__ Kh, const __nv_bfloat16* __restrict__ Kl,
               const __nv_bfloat16* __restrict__ Vh, const __nv_bfloat16* __restrict__ Vl,
               __nv_bfloat16* __restrict__ Oh, __nv_bfloat16* __restrict__ Ol)
{
    extern __shared__ char smem[];
    const uint32_t sb = (uint32_t)__cvta_generic_to_shared(smem);
    const int tid = threadIdx.x, w = tid >> 5, lane = tid & 31;
    const int qt = (int)(gridDim.x - 1 - blockIdx.x);
    const int bh = blockIdx.y, b = bh >> 4, h = bh & 15;
    const size_t gbase = (size_t)(b * SS) * EE + h * 64;

    const __nv_bfloat16* kv[4] = { Kh, Kl, Vh, Vl };

    auto load_kv = [&](int chunk) {
        const uint32_t bufb = sb + 65536 + (uint32_t)((chunk % 3) * FKVB);
        #pragma unroll
        for (int i = 0; i < 4; ++i) {
            int idx = tid + i * 512;
            int t = idx >> 9, rr = (idx & 511) >> 3, s8 = idx & 7;
            cp16(bufb + t * 8192 + rr * 128 + (uint32_t)((s8 * 16) ^ ((rr & 7) << 4)),
                 kv[t] + gbase + (size_t)(chunk * 64 + rr) * EE + s8 * 8);
        }
    };

    #pragma unroll
    for (int i = 0; i < 8; ++i) {
        int idx = tid + i * 512;
        int t = idx >> 11, rr = (idx & 2047) >> 3, s8 = idx & 7;
        const __nv_bfloat16* src = (t ? Ql : Qh) + gbase + (size_t)(qt * 256 + rr) * EE + s8 * 8;
        cp16(sb + t * 32768 + rr * 128 + (uint32_t)((s8 * 16) ^ ((rr & 7) << 4)), src);
    }
    load_kv(0);
    cp_commit();
    load_kv(1);
    cp_commit();

    const int r8 = lane & 7, g = lane >> 3;
    const int arow = w * 16 + r8 + (g & 1) * 8;
    const uint32_t axor = (uint32_t)((arow & 7) << 4);
    const int acolg = (g >> 1) * 16;
    const int brow = r8 + (g >> 1) * 8;
    const uint32_t bxor = (uint32_t)((brow & 7) << 4);
    const int bcolg = (g & 1) * 16;
    const int vrow = r8 + (g & 1) * 8;
    const uint32_t vxor = (uint32_t)((vrow & 7) << 4);
    const int vcolg = (g >> 1) * 16;

    float oacc[8][4];
    #pragma unroll
    for (int j = 0; j < 8; ++j)
        #pragma unroll
        for (int e = 0; e < 4; ++e) oacc[j][e] = 0.f;
    float m0 = NEG_INF, m1 = NEG_INF, l0 = 0.f, l1 = 0.f;

    const int nch = 4 * qt + 4;
    const int wminrow = qt * 256 + w * 16;

    for (int c = 0; c < nch; ++c) {
        asm volatile("cp.async.wait_group 1;" ::: "memory");
        __syncthreads();

        if (c + 2 < nch) load_kv(c + 2);
        cp_commit();

        if (c * 64 <= wminrow + 15) {
            const uint32_t bufb = sb + 65536 + (uint32_t)((c % 3) * FKVB);
            float sacc[8][4];
            #pragma unroll
            for (int j = 0; j < 8; ++j)
                #pragma unroll
                for (int e = 0; e < 4; ++e) sacc[j][e] = 0.f;

            // ---- S' = (Q*qscale) K^T  (bf16x3; already in log2 domain) ----
            #pragma unroll
            for (int ks = 0; ks < 4; ++ks) {
                uint32_t aH[4], aL[4];
                const uint32_t ao = (uint32_t)(arow * 128) + ((uint32_t)(ks * 32 + acolg) ^ axor);
                ldsm4(aH, sb + ao);
                ldsm4(aL, sb + 32768 + ao);
                const uint32_t colB = (uint32_t)(ks * 32 + bcolg) ^ bxor;
                #pragma unroll
                for (int nf2 = 0; nf2 < 4; ++nf2) {
                    uint32_t bH[4], bL[4];
                    const uint32_t ro = (uint32_t)((brow + nf2 * 16) * 128) + colB;
                    ldsm4(bH, bufb + ro);
                    ldsm4(bL, bufb + 8192 + ro);
                    #pragma unroll
                    for (int j = 0; j < 2; ++j) {
                        float* cc = sacc[nf2 * 2 + j];
                        mma16816(cc, aH, &bH[j * 2]);
                        mma16816(cc, aH, &bL[j * 2]);
                        mma16816(cc, aL, &bH[j * 2]);
                    }
                }
            }

            // ---- mask + online softmax (base-2) ----
            const int row0 = wminrow + (lane >> 2);
            if (c * 64 + 63 > wminrow) {
                #pragma unroll
                for (int j = 0; j < 8; ++j) {
                    int col = c * 64 + j * 8 + (lane & 3) * 2;
                    if (col     > row0)     sacc[j][0] = NEG_INF;
                    if (col + 1 > row0)     sacc[j][1] = NEG_INF;
                    if (col     > row0 + 8) sacc[j][2] = NEG_INF;
                    if (col + 1 > row0 + 8) sacc[j][3] = NEG_INF;
                }
            }
            float t0 = NEG_INF, t1 = NEG_INF;
            #pragma unroll
            for (int j = 0; j < 8; ++j) {
                t0 = fmaxf(t0, fmaxf(sacc[j][0], sacc[j][1]));
                t1 = fmaxf(t1, fmaxf(sacc[j][2], sacc[j][3]));
            }
            t0 = fmaxf(t0, __shfl_xor_sync(0xffffffffu, t0, 1));
            t0 = fmaxf(t0, __shfl_xor_sync(0xffffffffu, t0, 2));
            t1 = fmaxf(t1, __shfl_xor_sync(0xffffffffu, t1, 1));
            t1 = fmaxf(t1, __shfl_xor_sync(0xffffffffu, t1, 2));

            const float mn0 = fmaxf(m0, t0), mn1 = fmaxf(m1, t1);
            const float cr0 = exp2f(m0 - mn0), cr1 = exp2f(m1 - mn1);
            float s0 = 0.f, s1 = 0.f;
            #pragma unroll
            for (int j = 0; j < 8; ++j) {
                float p0 = exp2f(sacc[j][0] - mn0); sacc[j][0] = p0; s0 += p0;
                float p1 = exp2f(sacc[j][1] - mn0); sacc[j][1] = p1; s0 += p1;
                float p2 = exp2f(sacc[j][2] - mn1); sacc[j][2] = p2; s1 += p2;
                float p3 = exp2f(sacc[j][3] - mn1); sacc[j][3] = p3; s1 += p3;
            }
            s0 += __shfl_xor_sync(0xffffffffu, s0, 1);
            s0 += __shfl_xor_sync(0xffffffffu, s0, 2);
            s1 += __shfl_xor_sync(0xffffffffu, s1, 1);
            s1 += __shfl_xor_sync(0xffffffffu, s1, 2);
            l0 = l0 * cr0 + s0; l1 = l1 * cr1 + s1;
            m0 = mn0; m1 = mn1;
            #pragma unroll
            for (int j = 0; j < 8; ++j) {
                oacc[j][0] *= cr0; oacc[j][1] *= cr0;
                oacc[j][2] *= cr1; oacc[j][3] *= cr1;
            }

            // ---- O += P V  (P single fp16, V fp16 hi/lo, 2 terms) ----
            #pragma unroll
            for (int ks = 0; ks < 4; ++ks) {
                uint32_t aP[4];
                aP[0] = packh2(sacc[2*ks][0],   sacc[2*ks][1]);
                aP[1] = packh2(sacc[2*ks][2],   sacc[2*ks][3]);
                aP[2] = packh2(sacc[2*ks+1][0], sacc[2*ks+1][1]);
                aP[3] = packh2(sacc[2*ks+1][2], sacc[2*ks+1][3]);
                const uint32_t rbase = (uint32_t)((ks * 16 + vrow) * 128);
                #pragma unroll
                for (int nf2 = 0; nf2 < 4; ++nf2) {
                    uint32_t vH[4], vL[4];
                    const uint32_t vo = rbase + ((uint32_t)(nf2 * 32 + vcolg) ^ vxor);
                    ldsm4t(vH, bufb + 16384 + vo);
                    ldsm4t(vL, bufb + 24576 + vo);
                    #pragma unroll
                    for (int j = 0; j < 2; ++j) {
                        float* cc = oacc[nf2 * 2 + j];
                        mma16816h(cc, aP, &vH[j * 2]);
                        mma16816h(cc, aP, &vL[j * 2]);
                    }
                }
            }
        }
    }

    const float inv0 = 1.f / l0, inv1 = 1.f / l1;
    const int orow = qt * 256 + w * 16 + (lane >> 2);
    const int ocol = (lane & 3) * 2;
    #pragma unroll
    for (int j = 0; j < 8; ++j) {
        uint32_t h0, lo0, h1, lo1;
        splitpack(oacc[j][0] * inv0, oacc[j][1] * inv0, h0, lo0);
        splitpack(oacc[j][2] * inv1, oacc[j][3] * inv1, h1, lo1);
        size_t a0 = gbase + (size_t)orow * EE + j * 8 + ocol;
        size_t a1 = a0 + (size_t)8 * EE;
        *(uint32_t*)&Oh[a0] = h0; *(uint32_t*)&Ol[a0] = lo0;
        *(uint32_t*)&Oh[a1] = h1; *(uint32_t*)&Ol[a1] = lo1;
    }
}

// ---------------------------------------------------------------------------
extern "C" void kernel_launch(void* const* d_in, const int* in_sizes, int n_in,
                              void* d_out, int out_size)
{
    const float* x   = (const float*)d_in[0];
    const float* w_q = (const float*)d_in[2];
    const float* w_k = (const float*)d_in[3];
    const float* w_v = (const float*)d_in[4];
    const float* w_o = (const float*)d_in[5];
    const float* b_o = (const float*)d_in[6];
    float* out = (float*)d_out;

    __nv_bfloat16 *xh, *xl, *qkvh, *qkvl, *ah, *al, *wh, *wl;
    cudaGetSymbolAddress((void**)&xh,   g_xh);
    cudaGetSymbolAddress((void**)&xl,   g_xl);
    cudaGetSymbolAddress((void**)&qkvh, g_qkvh);
    cudaGetSymbolAddress((void**)&qkvl, g_qkvl);
    cudaGetSymbolAddress((void**)&ah,   g_ah);
    cudaGetSymbolAddress((void**)&al,   g_al);
    cudaGetSymbolAddress((void**)&wh,   g_wh);
    cudaGetSymbolAddress((void**)&wl,   g_wl);

    const int nblk = (N4X + 4 * N4W) / 256;
    split_all<<<nblk, 256>>>((const float4*)x,
                             (const float4*)w_q, (const float4*)w_k,
                             (const float4*)w_v, (const float4*)w_o,
                             (uint2*)xh, (uint2*)xl, (uint2*)wh, (uint2*)wl);

    const int gsmem = 2 * GSTAGE;        // 196608
    cudaFuncSetAttribute(mma_gemm<true>,  cudaFuncAttributeMaxDynamicSharedMemorySize, gsmem);
    cudaFuncSetAttribute(mma_gemm<false>, cudaFuncAttributeMaxDynamicSharedMemorySize, gsmem);
    dim3 gq(3 * EE / 256, ROWS / 128);   // (12, 64)
    mma_gemm<true><<<gq, 256, gsmem>>>(xh, xl, wh, wl, nullptr, nullptr, qkvh, qkvl);

    const size_t TS = (size_t)ROWS * EE;
    const int fsmem = 65536 + 3 * FKVB;  // 163840
    cudaFuncSetAttribute(flash_mma, cudaFuncAttributeMaxDynamicSharedMemorySize, fsmem);
    dim3 fgrid(SS / 256, BB * HH);
    flash_mma<<<fgrid, 512, fsmem>>>(qkvh, qkvl, qkvh + TS, qkvl + TS,
                                     qkvh + 2 * TS, qkvl + 2 * TS, ah, al);

    dim3 gg(EE / 256, ROWS / 128);       // (4, 64)
    mma_gemm<false><<<gg, 256, gsmem>>>(ah, al, wh + 3ull*EE*EE, wl + 3ull*EE*EE,
                                        b_o, out, nullptr, nullptr);
}

// round 14
// speedup vs baseline: 1.2626x; 1.0563x over previous
#include <cuda_runtime.h>
#include <cuda_bf16.h>
#include <cuda_fp16.h>
#include <math.h>
#include <stdint.h>

#define BB 4
#define SS 2048
#define EE 1024
#define HH 16
#define DD 64
#define ROWS (BB*SS)          // 8192

#define NEG_INF (__int_as_float(0xff800000))
#define QSCALE 0.18033688011112042f   // 0.125 * log2(e)

// ---------------- scratch (device globals: no runtime allocation) ----------
__device__ __align__(16) __nv_bfloat16 g_xh[ROWS*EE];
__device__ __align__(16) __nv_bfloat16 g_xl[ROWS*EE];
__device__ __align__(16) __nv_bfloat16 g_qkvh[3u*ROWS*EE];   // V slice holds fp16
__device__ __align__(16) __nv_bfloat16 g_qkvl[3u*ROWS*EE];
__device__ __align__(16) __half       g_att[ROWS*EE];        // attention out, fp16
__device__ __align__(16) __nv_bfloat16 g_wh[4u*EE*EE];       // w_o slice holds fp16
__device__ __align__(16) __nv_bfloat16 g_wl[4u*EE*EE];

#define N4X (ROWS*EE/4)
#define N4W (EE*EE/4)

// ---------------------------------------------------------------------------
// Fused fp32 split: x + w_q/w_k/w_v -> bf16 hi/lo ; w_o -> fp16 hi/lo
// ---------------------------------------------------------------------------
__global__ __launch_bounds__(256)
void split_all(const float4* __restrict__ x,
               const float4* __restrict__ w0, const float4* __restrict__ w1,
               const float4* __restrict__ w2, const float4* __restrict__ w3,
               uint2* __restrict__ xh, uint2* __restrict__ xl,
               uint2* __restrict__ wh, uint2* __restrict__ wl)
{
    int i = blockIdx.x * 256 + threadIdx.x;
    const float4* src; uint2 *dh, *dl;
    bool fp16mode = false;
    if (i < N4X) {
        src = x + i; dh = xh + i; dl = xl + i;
    } else {
        int j = i - N4X;
        int t = j >> 18;
        int loc = j & (N4W - 1);
        const float4* ws[4] = {w0, w1, w2, w3};
        src = ws[t] + loc;
        dh = wh + (size_t)t * N4W + loc;
        dl = wl + (size_t)t * N4W + loc;
        fp16mode = (t == 3);
    }
    float4 v = *src;
    float vv[4] = {v.x, v.y, v.z, v.w};
    unsigned hu[4], lu[4];
    if (fp16mode) {
        #pragma unroll
        for (int j = 0; j < 4; ++j) {
            __half h = __float2half_rn(vv[j]);
            __half l = __float2half_rn(vv[j] - __half2float(h));
            hu[j] = (unsigned)__half_as_ushort(h);
            lu[j] = (unsigned)__half_as_ushort(l);
        }
    } else {
        #pragma unroll
        for (int j = 0; j < 4; ++j) {
            __nv_bfloat16 h = __float2bfloat16(vv[j]);
            __nv_bfloat16 l = __float2bfloat16(vv[j] - __bfloat162float(h));
            hu[j] = (unsigned)__bfloat16_as_ushort(h);
            lu[j] = (unsigned)__bfloat16_as_ushort(l);
        }
    }
    uint2 ho, lv;
    ho.x = hu[0] | (hu[1] << 16); ho.y = hu[2] | (hu[3] << 16);
    lv.x = lu[0] | (lu[1] << 16); lv.y = lu[2] | (lu[3] << 16);
    *dh = ho; *dl = lv;
}

// ---------------------------------------------------------------------------
// mma.sync helpers
// ---------------------------------------------------------------------------
__device__ __forceinline__ void cp16(uint32_t saddr, const void* gptr) {
    asm volatile("cp.async.cg.shared.global [%0], [%1], 16;"
                 :: "r"(saddr), "l"(gptr));
}
__device__ __forceinline__ void cp_commit() {
    asm volatile("cp.async.commit_group;" ::: "memory");
}
__device__ __forceinline__ void ldsm4(uint32_t* r, uint32_t addr) {
    asm volatile("ldmatrix.sync.aligned.m8n8.x4.shared.b16 {%0,%1,%2,%3}, [%4];"
                 : "=r"(r[0]), "=r"(r[1]), "=r"(r[2]), "=r"(r[3]) : "r"(addr));
}
__device__ __forceinline__ void ldsm4t(uint32_t* r, uint32_t addr) {
    asm volatile("ldmatrix.sync.aligned.m8n8.x4.trans.shared.b16 {%0,%1,%2,%3}, [%4];"
                 : "=r"(r[0]), "=r"(r[1]), "=r"(r[2]), "=r"(r[3]) : "r"(addr));
}
__device__ __forceinline__ void mma16816(float* c, const uint32_t* a, const uint32_t* b) {
    asm volatile(
        "mma.sync.aligned.m16n8k16.row.col.f32.bf16.bf16.f32 "
        "{%0,%1,%2,%3}, {%4,%5,%6,%7}, {%8,%9}, {%0,%1,%2,%3};"
        : "+f"(c[0]), "+f"(c[1]), "+f"(c[2]), "+f"(c[3])
        : "r"(a[0]), "r"(a[1]), "r"(a[2]), "r"(a[3]), "r"(b[0]), "r"(b[1]));
}
__device__ __forceinline__ void mma16816h(float* c, const uint32_t* a, const uint32_t* b) {
    asm volatile(
        "mma.sync.aligned.m16n8k16.row.col.f32.f16.f16.f32 "
        "{%0,%1,%2,%3}, {%4,%5,%6,%7}, {%8,%9}, {%0,%1,%2,%3};"
        : "+f"(c[0]), "+f"(c[1]), "+f"(c[2]), "+f"(c[3])
        : "r"(a[0]), "r"(a[1]), "r"(a[2]), "r"(a[3]), "r"(b[0]), "r"(b[1]));
}
__device__ __forceinline__ void splitpack(float a, float b, uint32_t& hi, uint32_t& lo) {
    __nv_bfloat16 ha = __float2bfloat16(a), hb = __float2bfloat16(b);
    uint32_t hh = (uint32_t)__bfloat16_as_ushort(ha) |
                  ((uint32_t)__bfloat16_as_ushort(hb) << 16);
    __nv_bfloat16 la = __float2bfloat16(a - __bfloat162float(ha));
    __nv_bfloat16 lb = __float2bfloat16(b - __bfloat162float(hb));
    uint32_t ll = (uint32_t)__bfloat16_as_ushort(la) |
                  ((uint32_t)__bfloat16_as_ushort(lb) << 16);
    hi = hh; lo = ll;
}
__device__ __forceinline__ void splitpackh(float a, float b, uint32_t& hi, uint32_t& lo) {
    __half ha = __float2half_rn(a), hb = __float2half_rn(b);
    uint32_t hh = (uint32_t)__half_as_ushort(ha) |
                  ((uint32_t)__half_as_ushort(hb) << 16);
    __half la = __float2half_rn(a - __half2float(ha));
    __half lb = __float2half_rn(b - __half2float(hb));
    uint32_t ll = (uint32_t)__half_as_ushort(la) |
                  ((uint32_t)__half_as_ushort(lb) << 16);
    hi = hh; lo = ll;
}
__device__ __forceinline__ uint32_t packh2(float a, float b) {
    uint32_t r;
    asm("cvt.rn.f16x2.f32 %0, %1, %2;" : "=r"(r) : "f"(b), "f"(a));
    return r;
}

#define NKC (EE/64)

// ===========================================================================
// QKV GEMM (round-13 proven): CTA 128x256, 8 warps (2x4), warp 64x64,
// 2-stage 96KB. bf16x3. Epilogue: Q scaled bf16 h/l, K bf16 h/l, V fp16 h/l.
// ===========================================================================
#define OF_AL 16384
#define OF_BH 32768
#define OF_BL 65536
#define GSTAGE 98304

__global__ __launch_bounds__(256, 1)
void mma_gemm_qkv(const __nv_bfloat16* __restrict__ Ah0, const __nv_bfloat16* __restrict__ Al0,
                  const __nv_bfloat16* __restrict__ Wh0, const __nv_bfloat16* __restrict__ Wl0,
                  __nv_bfloat16* __restrict__ Ch0, __nv_bfloat16* __restrict__ Cl0)
{
    extern __shared__ char smem[];
    const uint32_t sb = (uint32_t)__cvta_generic_to_shared(smem);
    const int K = EE, N = EE;

    const int tid = threadIdx.x;
    const int w = tid >> 5, lane = tid & 31;
    const int wm = w & 1, wn = w >> 1;
    const int wsel = blockIdx.x >> 2;
    const int bm = blockIdx.y * 128;
    const int bn = (blockIdx.x & 3) * 256;

    const __nv_bfloat16* Ahp = Ah0 + (size_t)bm * K;
    const __nv_bfloat16* Alp = Al0 + (size_t)bm * K;
    const __nv_bfloat16* Bhp = Wh0 + (size_t)wsel * EE * EE + (size_t)bn * K;
    const __nv_bfloat16* Blp = Wl0 + (size_t)wsel * EE * EE + (size_t)bn * K;
    __nv_bfloat16* Ch = Ch0 + (size_t)wsel * ROWS * EE;
    __nv_bfloat16* Cl = Cl0 + (size_t)wsel * ROWS * EE;

    const int r8 = lane & 7, g = lane >> 3;
    const int arow = wm * 64 + r8 + (g & 1) * 8;
    const int acolg = (g >> 1) * 16;
    const uint32_t axor = (uint32_t)((arow & 7) << 4);
    const int brow = wn * 64 + r8 + (g >> 1) * 8;
    const int bcolg = (g & 1) * 16;
    const uint32_t bxor = (uint32_t)((brow & 7) << 4);

    float acc[4][8][4];
    #pragma unroll
    for (int a = 0; a < 4; ++a)
        #pragma unroll
        for (int b = 0; b < 8; ++b)
            #pragma unroll
            for (int c = 0; c < 4; ++c) acc[a][b][c] = 0.f;

    auto load_stage = [&](int slot, int kc) {
        const uint32_t sbase = sb + (uint32_t)(slot * GSTAGE);
        #pragma unroll
        for (int i = 0; i < 24; ++i) {
            int idx = tid + i * 256;
            const __nv_bfloat16* src;
            uint32_t toff; int local;
            if (i < 4)       { local = idx;        src = Ahp; toff = 0; }
            else if (i < 8)  { local = idx - 1024; src = Alp; toff = OF_AL; }
            else if (i < 16) { local = idx - 2048; src = Bhp; toff = OF_BH; }
            else             { local = idx - 4096; src = Blp; toff = OF_BL; }
            int row = local >> 3, s8 = local & 7;
            cp16(sbase + toff + (uint32_t)(row * 128 + ((s8 * 16) ^ ((row & 7) << 4))),
                 src + (size_t)row * K + kc * 64 + s8 * 8);
        }
        cp_commit();
    };

    load_stage(0, 0);

    for (int kc = 0; kc < NKC; ++kc) {
        if (kc + 1 < NKC) {
            load_stage((kc + 1) & 1, kc + 1);
            asm volatile("cp.async.wait_group 1;" ::: "memory");
        } else {
            asm volatile("cp.async.wait_group 0;" ::: "memory");
        }
        __syncthreads();

        const uint32_t stg = sb + (uint32_t)((kc & 1) * GSTAGE);

        #pragma unroll
        for (int ks = 0; ks < 4; ++ks) {
            uint32_t aH[4][4], aL[4][4];
            const uint32_t colA = (uint32_t)(ks * 32 + acolg) ^ axor;
            const uint32_t colB = (uint32_t)(ks * 32 + bcolg) ^ bxor;
            #pragma unroll
            for (int mf = 0; mf < 4; ++mf) {
                const uint32_t ro = (uint32_t)((arow + mf * 16) * 128) + colA;
                ldsm4(aH[mf], stg + ro);
                ldsm4(aL[mf], stg + OF_AL + ro);
            }
            #pragma unroll
            for (int nf2 = 0; nf2 < 4; ++nf2) {
                uint32_t bH[4], bL[4];
                const uint32_t ro = (uint32_t)((brow + nf2 * 16) * 128) + colB;
                ldsm4(bH, stg + OF_BH + ro);
                ldsm4(bL, stg + OF_BL + ro);
                #pragma unroll
                for (int mf = 0; mf < 4; ++mf)
                    #pragma unroll
                    for (int j = 0; j < 2; ++j) {
                        float* c = acc[mf][nf2 * 2 + j];
                        mma16816(c, aH[mf], &bH[j * 2]);
                        mma16816(c, aH[mf], &bL[j * 2]);
                        mma16816(c, aL[mf], &bH[j * 2]);
                    }
            }
        }
        __syncthreads();
    }

    const int row0 = bm + wm * 64 + (lane >> 2);
    const int col0 = bn + wn * 64 + (lane & 3) * 2;
    const float esc = (wsel == 0) ? QSCALE : 1.0f;
    #pragma unroll
    for (int mf = 0; mf < 4; ++mf)
        #pragma unroll
        for (int nf = 0; nf < 8; ++nf) {
            const int r = row0 + mf * 16;
            const int col = col0 + nf * 8;
            float f0 = acc[mf][nf][0] * esc, f1 = acc[mf][nf][1] * esc;
            float f2 = acc[mf][nf][2] * esc, f3 = acc[mf][nf][3] * esc;
            uint32_t h0, l0, h1, l1;
            if (wsel == 2) {          // V: fp16 hi/lo
                splitpackh(f0, f1, h0, l0);
                splitpackh(f2, f3, h1, l1);
            } else {                  // Q (scaled) / K: bf16 hi/lo
                splitpack(f0, f1, h0, l0);
                splitpack(f2, f3, h1, l1);
            }
            *(uint32_t*)&Ch[(size_t)r * N + col]       = h0;
            *(uint32_t*)&Cl[(size_t)r * N + col]       = l0;
            *(uint32_t*)&Ch[(size_t)(r + 8) * N + col] = h1;
            *(uint32_t*)&Cl[(size_t)(r + 8) * N + col] = l1;
        }
}

// ===========================================================================
// O-projection GEMM: 2-term fp16 (A single fp16, W fp16 hi/lo).
// CTA 128x128, 8 warps (4x2), warp 32x64, 2-stage x 48KB = 96KB => 2 CTAs/SM.
// ===========================================================================
#define O_BH 16384
#define O_BL 32768
#define O_STAGE 49152

__global__ __launch_bounds__(256, 2)
void mma_gemm_o(const __half* __restrict__ A0,
                const __nv_bfloat16* __restrict__ Wh0, const __nv_bfloat16* __restrict__ Wl0,
                const float* __restrict__ bias, float* __restrict__ C)
{
    extern __shared__ char smem[];
    const uint32_t sb = (uint32_t)__cvta_generic_to_shared(smem);
    const int K = EE, N = EE;

    const int tid = threadIdx.x;
    const int w = tid >> 5, lane = tid & 31;
    const int wm = w & 3, wn = w >> 2;               // 4x2: warp tile 32x64
    const int bm = blockIdx.y * 128;
    const int bn = blockIdx.x * 128;

    const __half* Ap = A0 + (size_t)bm * K;
    const __nv_bfloat16* Bhp = Wh0 + (size_t)bn * K;
    const __nv_bfloat16* Blp = Wl0 + (size_t)bn * K;

    const int r8 = lane & 7, g = lane >> 3;
    const int arow = wm * 32 + r8 + (g & 1) * 8;
    const int acolg = (g >> 1) * 16;
    const uint32_t axor = (uint32_t)((arow & 7) << 4);
    const int brow = wn * 64 + r8 + (g >> 1) * 8;
    const int bcolg = (g & 1) * 16;
    const uint32_t bxor = (uint32_t)((brow & 7) << 4);

    float acc[2][8][4];
    #pragma unroll
    for (int a = 0; a < 2; ++a)
        #pragma unroll
        for (int b = 0; b < 8; ++b)
            #pragma unroll
            for (int c = 0; c < 4; ++c) acc[a][b][c] = 0.f;

    // 3 tiles x 1024 segs = 3072 segs / 256 threads = 12 each
    auto load_stage = [&](int slot, int kc) {
        const uint32_t sbase = sb + (uint32_t)(slot * O_STAGE);
        #pragma unroll
        for (int i = 0; i < 12; ++i) {
            int idx = tid + i * 256;
            const void* src;
            uint32_t toff; int local;
            if (i < 4)      { local = idx;        toff = 0;
                              src = Ap  + (size_t)(local >> 3) * K + kc * 64 + (local & 7) * 8; }
            else if (i < 8) { local = idx - 1024; toff = O_BH;
                              src = Bhp + (size_t)(local >> 3) * K + kc * 64 + (local & 7) * 8; }
            else            { local = idx - 2048; toff = O_BL;
                              src = Blp + (size_t)(local >> 3) * K + kc * 64 + (local & 7) * 8; }
            int row = local >> 3, s8 = local & 7;
            cp16(sbase + toff + (uint32_t)(row * 128 + ((s8 * 16) ^ ((row & 7) << 4))), src);
        }
        cp_commit();
    };

    load_stage(0, 0);

    for (int kc = 0; kc < NKC; ++kc) {
        if (kc + 1 < NKC) {
            load_stage((kc + 1) & 1, kc + 1);
            asm volatile("cp.async.wait_group 1;" ::: "memory");
        } else {
            asm volatile("cp.async.wait_group 0;" ::: "memory");
        }
        __syncthreads();

        const uint32_t stg = sb + (uint32_t)((kc & 1) * O_STAGE);

        #pragma unroll
        for (int ks = 0; ks < 4; ++ks) {
            uint32_t aF[2][4];
            const uint32_t colA = (uint32_t)(ks * 32 + acolg) ^ axor;
            const uint32_t colB = (uint32_t)(ks * 32 + bcolg) ^ bxor;
            #pragma unroll
            for (int mf = 0; mf < 2; ++mf)
                ldsm4(aF[mf], stg + (uint32_t)((arow + mf * 16) * 128) + colA);
            #pragma unroll
            for (int nf2 = 0; nf2 < 4; ++nf2) {
                uint32_t bH[4], bL[4];
                const uint32_t ro = (uint32_t)((brow + nf2 * 16) * 128) + colB;
                ldsm4(bH, stg + O_BH + ro);
                ldsm4(bL, stg + O_BL + ro);
                #pragma unroll
                for (int mf = 0; mf < 2; ++mf)
                    #pragma unroll
                    for (int j = 0; j < 2; ++j) {
                        float* c = acc[mf][nf2 * 2 + j];
                        mma16816h(c, aF[mf], &bH[j * 2]);
                        mma16816h(c, aF[mf], &bL[j * 2]);
                    }
            }
        }
        __syncthreads();
    }

    const int row0 = bm + wm * 32 + (lane >> 2);
    const int col0 = bn + wn * 64 + (lane & 3) * 2;
    #pragma unroll
    for (int mf = 0; mf < 2; ++mf)
        #pragma unroll
        for (int nf = 0; nf < 8; ++nf) {
            const int r = row0 + mf * 16;
            const int col = col0 + nf * 8;
            float b0 = bias[col], b1 = bias[col + 1];
            float2 v0, v1;
            v0.x = acc[mf][nf][0] + b0; v0.y = acc[mf][nf][1] + b1;
            v1.x = acc[mf][nf][2] + b0; v1.y = acc[mf][nf][3] + b1;
            *(float2*)&C[(size_t)r * N + col]       = v0;
            *(float2*)&C[(size_t)(r + 8) * N + col] = v1;
        }
}

// ---------------------------------------------------------------------------
// Tensor-core causal flash attention (round-13 mainloop).
// Epilogue now writes att as single fp16.
// ---------------------------------------------------------------------------
#define FKVB 32768

__global__ __launch_bounds__(512, 1)
void flash_mma(const __nv_bfloat16* __restrict__ Qh, const __nv_bfloat16* __restrict__ Ql,
               const __nv_bfloat16* __restrict__ Kh, const __nv_bfloat16* __restrict__ Kl,
               const __nv_bfloat16* __restrict__ Vh, const __nv_bfloat16* __restrict__ Vl,
               __half* __restrict__ O)
{
    extern __shared__ char smem[];
    const uint32_t sb = (uint32_t)__cvta_generic_to_shared(smem);
    const int tid = threadIdx.x, w = tid >> 5, lane = tid & 31;
    const int qt = (int)(gridDim.x - 1 - blockIdx.x);
    const int bh = blockIdx.y, b = bh >> 4, h = bh & 15;
    const size_t gbase = (size_t)(b * SS) * EE + h * 64;

    const __nv_bfloat16* kv[4] = { Kh, Kl, Vh, Vl };

    auto load_kv = [&](int chunk) {
        const uint32_t bufb = sb + 65536 + (uint32_t)((chunk % 3) * FKVB);
        #pragma unroll
        for (int i = 0; i < 4; ++i) {
            int idx = tid + i * 512;
            int t = idx >> 9, rr = (idx & 511) >> 3, s8 = idx & 7;
            cp16(bufb + t * 8192 + rr * 128 + (uint32_t)((s8 * 16) ^ ((rr & 7) << 4)),
                 kv[t] + gbase + (size_t)(chunk * 64 + rr) * EE + s8 * 8);
        }
    };

    #pragma unroll
    for (int i = 0; i < 8; ++i) {
        int idx = tid + i * 512;
        int t = idx >> 11, rr = (idx & 2047) >> 3, s8 = idx & 7;
        const __nv_bfloat16* src = (t ? Ql : Qh) + gbase + (size_t)(qt * 256 + rr) * EE + s8 * 8;
        cp16(sb + t * 32768 + rr * 128 + (uint32_t)((s8 * 16) ^ ((rr & 7) << 4)), src);
    }
    load_kv(0);
    cp_commit();
    load_kv(1);
    cp_commit();

    const int r8 = lane & 7, g = lane >> 3;
    const int arow = w * 16 + r8 + (g & 1) * 8;
    const uint32_t axor = (uint32_t)((arow & 7) << 4);
    const int acolg = (g >> 1) * 16;
    const int brow = r8 + (g >> 1) * 8;
    const uint32_t bxor = (uint32_t)((brow & 7) << 4);
    const int bcolg = (g & 1) * 16;
    const int vrow = r8 + (g & 1) * 8;
    const uint32_t vxor = (uint32_t)((vrow & 7) << 4);
    const int vcolg = (g >> 1) * 16;

    float oacc[8][4];
    #pragma unroll
    for (int j = 0; j < 8; ++j)
        #pragma unroll
        for (int e = 0; e < 4; ++e) oacc[j][e] = 0.f;
    float m0 = NEG_INF, m1 = NEG_INF, l0 = 0.f, l1 = 0.f;

    const int nch = 4 * qt + 4;
    const int wminrow = qt * 256 + w * 16;

    for (int c = 0; c < nch; ++c) {
        asm volatile("cp.async.wait_group 1;" ::: "memory");
        __syncthreads();

        if (c + 2 < nch) load_kv(c + 2);
        cp_commit();

        if (c * 64 <= wminrow + 15) {
            const uint32_t bufb = sb + 65536 + (uint32_t)((c % 3) * FKVB);
            float sacc[8][4];
            #pragma unroll
            for (int j = 0; j < 8; ++j)
                #pragma unroll
                for (int e = 0; e < 4; ++e) sacc[j][e] = 0.f;

            #pragma unroll
            for (int ks = 0; ks < 4; ++ks) {
                uint32_t aH[4], aL[4];
                const uint32_t ao = (uint32_t)(arow * 128) + ((uint32_t)(ks * 32 + acolg) ^ axor);
                ldsm4(aH, sb + ao);
                ldsm4(aL, sb + 32768 + ao);
                const uint32_t colB = (uint32_t)(ks * 32 + bcolg) ^ bxor;
                #pragma unroll
                for (int nf2 = 0; nf2 < 4; ++nf2) {
                    uint32_t bH[4], bL[4];
                    const uint32_t ro = (uint32_t)((brow + nf2 * 16) * 128) + colB;
                    ldsm4(bH, bufb + ro);
                    ldsm4(bL, bufb + 8192 + ro);
                    #pragma unroll
                    for (int j = 0; j < 2; ++j) {
                        float* cc = sacc[nf2 * 2 + j];
                        mma16816(cc, aH, &bH[j * 2]);
                        mma16816(cc, aH, &bL[j * 2]);
                        mma16816(cc, aL, &bH[j * 2]);
                    }
                }
            }

            const int row0 = wminrow + (lane >> 2);
            if (c * 64 + 63 > wminrow) {
                #pragma unroll
                for (int j = 0; j < 8; ++j) {
                    int col = c * 64 + j * 8 + (lane & 3) * 2;
                    if (col     > row0)     sacc[j][0] = NEG_INF;
                    if (col + 1 > row0)     sacc[j][1] = NEG_INF;
                    if (col     > row0 + 8) sacc[j][2] = NEG_INF;
                    if (col + 1 > row0 + 8) sacc[j][3] = NEG_INF;
                }
            }
            float t0 = NEG_INF, t1 = NEG_INF;
            #pragma unroll
            for (int j = 0; j < 8; ++j) {
                t0 = fmaxf(t0, fmaxf(sacc[j][0], sacc[j][1]));
                t1 = fmaxf(t1, fmaxf(sacc[j][2], sacc[j][3]));
            }
            t0 = fmaxf(t0, __shfl_xor_sync(0xffffffffu, t0, 1));
            t0 = fmaxf(t0, __shfl_xor_sync(0xffffffffu, t0, 2));
            t1 = fmaxf(t1, __shfl_xor_sync(0xffffffffu, t1, 1));
            t1 = fmaxf(t1, __shfl_xor_sync(0xffffffffu, t1, 2));

            const float mn0 = fmaxf(m0, t0), mn1 = fmaxf(m1, t1);
            const float cr0 = exp2f(m0 - mn0), cr1 = exp2f(m1 - mn1);
            float s0 = 0.f, s1 = 0.f;
            #pragma unroll
            for (int j = 0; j < 8; ++j) {
                float p0 = exp2f(sacc[j][0] - mn0); sacc[j][0] = p0; s0 += p0;
                float p1 = exp2f(sacc[j][1] - mn0); sacc[j][1] = p1; s0 += p1;
                float p2 = exp2f(sacc[j][2] - mn1); sacc[j][2] = p2; s1 += p2;
                float p3 = exp2f(sacc[j][3] - mn1); sacc[j][3] = p3; s1 += p3;
            }
            s0 += __shfl_xor_sync(0xffffffffu, s0, 1);
            s0 += __shfl_xor_sync(0xffffffffu, s0, 2);
            s1 += __shfl_xor_sync(0xffffffffu, s1, 1);
            s1 += __shfl_xor_sync(0xffffffffu, s1, 2);
            l0 = l0 * cr0 + s0; l1 = l1 * cr1 + s1;
            m0 = mn0; m1 = mn1;
            #pragma unroll
            for (int j = 0; j < 8; ++j) {
                oacc[j][0] *= cr0; oacc[j][1] *= cr0;
                oacc[j][2] *= cr1; oacc[j][3] *= cr1;
            }

            #pragma unroll
            for (int ks = 0; ks < 4; ++ks) {
                uint32_t aP[4];
                aP[0] = packh2(sacc[2*ks][0],   sacc[2*ks][1]);
                aP[1] = packh2(sacc[2*ks][2],   sacc[2*ks][3]);
                aP[2] = packh2(sacc[2*ks+1][0], sacc[2*ks+1][1]);
                aP[3] = packh2(sacc[2*ks+1][2], sacc[2*ks+1][3]);
                const uint32_t rbase = (uint32_t)((ks * 16 + vrow) * 128);
                #pragma unroll
                for (int nf2 = 0; nf2 < 4; ++nf2) {
                    uint32_t vH[4], vL[4];
                    const uint32_t vo = rbase + ((uint32_t)(nf2 * 32 + vcolg) ^ vxor);
                    ldsm4t(vH, bufb + 16384 + vo);
                    ldsm4t(vL, bufb + 24576 + vo);
                    #pragma unroll
                    for (int j = 0; j < 2; ++j) {
                        float* cc = oacc[nf2 * 2 + j];
                        mma16816h(cc, aP, &vH[j * 2]);
                        mma16816h(cc, aP, &vL[j * 2]);
                    }
                }
            }
        }
    }

    const float inv0 = 1.f / l0, inv1 = 1.f / l1;
    const int orow = qt * 256 + w * 16 + (lane >> 2);
    const int ocol = (lane & 3) * 2;
    #pragma unroll
    for (int j = 0; j < 8; ++j) {
        uint32_t p0 = packh2(oacc[j][0] * inv0, oacc[j][1] * inv0);
        uint32_t p1 = packh2(oacc[j][2] * inv1, oacc[j][3] * inv1);
        size_t a0 = gbase + (size_t)orow * EE + j * 8 + ocol;
        size_t a1 = a0 + (size_t)8 * EE;
        *(uint32_t*)&O[a0] = p0;
        *(uint32_t*)&O[a1] = p1;
    }
}

// ---------------------------------------------------------------------------
extern "C" void kernel_launch(void* const* d_in, const int* in_sizes, int n_in,
                              void* d_out, int out_size)
{
    const float* x   = (const float*)d_in[0];
    const float* w_q = (const float*)d_in[2];
    const float* w_k = (const float*)d_in[3];
    const float* w_v = (const float*)d_in[4];
    const float* w_o = (const float*)d_in[5];
    const float* b_o = (const float*)d_in[6];
    float* out = (float*)d_out;

    __nv_bfloat16 *xh, *xl, *qkvh, *qkvl, *wh, *wl;
    __half *att;
    cudaGetSymbolAddress((void**)&xh,   g_xh);
    cudaGetSymbolAddress((void**)&xl,   g_xl);
    cudaGetSymbolAddress((void**)&qkvh, g_qkvh);
    cudaGetSymbolAddress((void**)&qkvl, g_qkvl);
    cudaGetSymbolAddress((void**)&att,  g_att);
    cudaGetSymbolAddress((void**)&wh,   g_wh);
    cudaGetSymbolAddress((void**)&wl,   g_wl);

    const int nblk = (N4X + 4 * N4W) / 256;
    split_all<<<nblk, 256>>>((const float4*)x,
                             (const float4*)w_q, (const float4*)w_k,
                             (const float4*)w_v, (const float4*)w_o,
                             (uint2*)xh, (uint2*)xl, (uint2*)wh, (uint2*)wl);

    const int gsmem = 2 * GSTAGE;        // 196608
    cudaFuncSetAttribute(mma_gemm_qkv, cudaFuncAttributeMaxDynamicSharedMemorySize, gsmem);
    dim3 gq(3 * EE / 256, ROWS / 128);   // (12, 64)
    mma_gemm_qkv<<<gq, 256, gsmem>>>(xh, xl, wh, wl, qkvh, qkvl);

    const size_t TS = (size_t)ROWS * EE;
    const int fsmem = 65536 + 3 * FKVB;  // 163840
    cudaFuncSetAttribute(flash_mma, cudaFuncAttributeMaxDynamicSharedMemorySize, fsmem);
    dim3 fgrid(SS / 256, BB * HH);
    flash_mma<<<fgrid, 512, fsmem>>>(qkvh, qkvl, qkvh + TS, qkvl + TS,
                                     qkvh + 2 * TS, qkvl + 2 * TS, att);

    const int osmem = 2 * O_STAGE;       // 98304 -> 2 CTAs/SM
    cudaFuncSetAttribute(mma_gemm_o, cudaFuncAttributeMaxDynamicSharedMemorySize, osmem);
    dim3 gg(EE / 128, ROWS / 128);       // (8, 64)
    mma_gemm_o<<<gg, 256, osmem>>>(att,
                                   wh + 3ull*EE*EE, wl + 3ull*EE*EE, b_o, out);
}

// round 15
// speedup vs baseline: 1.6719x; 1.3242x over previous
#include <cuda_runtime.h>
#include <cuda_bf16.h>
#include <cuda_fp16.h>
#include <math.h>
#include <stdint.h>

#define BB 4
#define SS 2048
#define EE 1024
#define HH 16
#define DD 64
#define ROWS (BB*SS)          // 8192

#define NEG_INF (__int_as_float(0xff800000))
#define QSCALE 0.18033688011112042f   // 0.125 * log2(e)

// ---------------- scratch (device globals: no runtime allocation) ----------
__device__ __align__(16) __half g_x16[ROWS*EE];          // x, single fp16
__device__ __align__(16) __half g_q[ROWS*EE];            // Q (scaled), single fp16
__device__ __align__(16) __half g_kvh[2u*ROWS*EE];       // K,V hi
__device__ __align__(16) __half g_kvl[2u*ROWS*EE];       // K,V lo
__device__ __align__(16) __half g_att[ROWS*EE];          // attention out, fp16
__device__ __align__(16) __half g_wh[4u*EE*EE];          // weights hi (fp16)
__device__ __align__(16) __half g_wl[4u*EE*EE];          // weights lo (fp16)

#define N4X (ROWS*EE/4)
#define N4W (EE*EE/4)

// ---------------------------------------------------------------------------
// Fused fp32 split: x -> single fp16 ; all 4 weights -> fp16 hi/lo
// ---------------------------------------------------------------------------
__global__ __launch_bounds__(256)
void split_all(const float4* __restrict__ x,
               const float4* __restrict__ w0, const float4* __restrict__ w1,
               const float4* __restrict__ w2, const float4* __restrict__ w3,
               uint2* __restrict__ x16,
               uint2* __restrict__ wh, uint2* __restrict__ wl)
{
    int i = blockIdx.x * 256 + threadIdx.x;
    if (i < N4X) {
        float4 v = x[i];
        uint2 o;
        asm("cvt.rn.f16x2.f32 %0, %1, %2;" : "=r"(o.x) : "f"(v.y), "f"(v.x));
        asm("cvt.rn.f16x2.f32 %0, %1, %2;" : "=r"(o.y) : "f"(v.w), "f"(v.z));
        x16[i] = o;
        return;
    }
    int j = i - N4X;
    int t = j >> 18;
    int loc = j & (N4W - 1);
    const float4* ws[4] = {w0, w1, w2, w3};
    float4 v = ws[t][loc];
    float vv[4] = {v.x, v.y, v.z, v.w};
    unsigned hu[4], lu[4];
    #pragma unroll
    for (int k = 0; k < 4; ++k) {
        __half h = __float2half_rn(vv[k]);
        __half l = __float2half_rn(vv[k] - __half2float(h));
        hu[k] = (unsigned)__half_as_ushort(h);
        lu[k] = (unsigned)__half_as_ushort(l);
    }
    uint2 ho, lv;
    ho.x = hu[0] | (hu[1] << 16); ho.y = hu[2] | (hu[3] << 16);
    lv.x = lu[0] | (lu[1] << 16); lv.y = lu[2] | (lu[3] << 16);
    wh[(size_t)t * N4W + loc] = ho;
    wl[(size_t)t * N4W + loc] = lv;
}

// ---------------------------------------------------------------------------
// mma.sync helpers
// ---------------------------------------------------------------------------
__device__ __forceinline__ void cp16(uint32_t saddr, const void* gptr) {
    asm volatile("cp.async.cg.shared.global [%0], [%1], 16;"
                 :: "r"(saddr), "l"(gptr));
}
__device__ __forceinline__ void cp_commit() {
    asm volatile("cp.async.commit_group;" ::: "memory");
}
__device__ __forceinline__ void ldsm4(uint32_t* r, uint32_t addr) {
    asm volatile("ldmatrix.sync.aligned.m8n8.x4.shared.b16 {%0,%1,%2,%3}, [%4];"
                 : "=r"(r[0]), "=r"(r[1]), "=r"(r[2]), "=r"(r[3]) : "r"(addr));
}
__device__ __forceinline__ void ldsm4t(uint32_t* r, uint32_t addr) {
    asm volatile("ldmatrix.sync.aligned.m8n8.x4.trans.shared.b16 {%0,%1,%2,%3}, [%4];"
                 : "=r"(r[0]), "=r"(r[1]), "=r"(r[2]), "=r"(r[3]) : "r"(addr));
}
__device__ __forceinline__ void mma16816h(float* c, const uint32_t* a, const uint32_t* b) {
    asm volatile(
        "mma.sync.aligned.m16n8k16.row.col.f32.f16.f16.f32 "
        "{%0,%1,%2,%3}, {%4,%5,%6,%7}, {%8,%9}, {%0,%1,%2,%3};"
        : "+f"(c[0]), "+f"(c[1]), "+f"(c[2]), "+f"(c[3])
        : "r"(a[0]), "r"(a[1]), "r"(a[2]), "r"(a[3]), "r"(b[0]), "r"(b[1]));
}
__device__ __forceinline__ void splitpackh(float a, float b, uint32_t& hi, uint32_t& lo) {
    __half ha = __float2half_rn(a), hb = __float2half_rn(b);
    uint32_t hh = (uint32_t)__half_as_ushort(ha) |
                  ((uint32_t)__half_as_ushort(hb) << 16);
    __half la = __float2half_rn(a - __half2float(ha));
    __half lb = __float2half_rn(b - __half2float(hb));
    uint32_t ll = (uint32_t)__half_as_ushort(la) |
                  ((uint32_t)__half_as_ushort(lb) << 16);
    hi = hh; lo = ll;
}
__device__ __forceinline__ uint32_t packh2(float a, float b) {
    uint32_t r;
    asm("cvt.rn.f16x2.f32 %0, %1, %2;" : "=r"(r) : "f"(b), "f"(a));
    return r;
}

#define NKC (EE/64)

// ===========================================================================
// 2-term fp16 GEMM core (proven O-GEMM shape): CTA 128x128, 8 warps (4x2),
// warp tile 32x64, 2-stage x 48KB = 96KB => 2 CTAs/SM.
// QKV=true : A = x fp16, W = wq/wk/wv hi/lo; epilogue Q fp16 (scaled) or
//            K/V fp16 hi/lo.
// QKV=false: A = att fp16, W = wo hi/lo; epilogue fp32 + bias.
// ===========================================================================
#define O_BH 16384
#define O_BL 32768
#define O_STAGE 49152

template<bool QKV>
__global__ __launch_bounds__(256, 2)
void mma_gemm(const __half* __restrict__ A0,
              const __half* __restrict__ Wh0, const __half* __restrict__ Wl0,
              const float* __restrict__ bias, float* __restrict__ C,
              __half* __restrict__ Q0,
              __half* __restrict__ KVh, __half* __restrict__ KVl)
{
    extern __shared__ char smem[];
    const uint32_t sb = (uint32_t)__cvta_generic_to_shared(smem);
    const int K = EE, N = EE;

    const int tid = threadIdx.x;
    const int w = tid >> 5, lane = tid & 31;
    const int wm = w & 3, wn = w >> 2;               // 4x2: warp tile 32x64
    const int wsel = QKV ? (blockIdx.x >> 3) : 0;
    const int bm = blockIdx.y * 128;
    const int bn = QKV ? ((blockIdx.x & 7) * 128) : (blockIdx.x * 128);

    const __half* Ap  = A0 + (size_t)bm * K;
    const __half* Bhp = Wh0 + (size_t)wsel * EE * EE + (size_t)bn * K;
    const __half* Blp = Wl0 + (size_t)wsel * EE * EE + (size_t)bn * K;

    const int r8 = lane & 7, g = lane >> 3;
    const int arow = wm * 32 + r8 + (g & 1) * 8;
    const int acolg = (g >> 1) * 16;
    const uint32_t axor = (uint32_t)((arow & 7) << 4);
    const int brow = wn * 64 + r8 + (g >> 1) * 8;
    const int bcolg = (g & 1) * 16;
    const uint32_t bxor = (uint32_t)((brow & 7) << 4);

    float acc[2][8][4];
    #pragma unroll
    for (int a = 0; a < 2; ++a)
        #pragma unroll
        for (int b = 0; b < 8; ++b)
            #pragma unroll
            for (int c = 0; c < 4; ++c) acc[a][b][c] = 0.f;

    auto load_stage = [&](int slot, int kc) {
        const uint32_t sbase = sb + (uint32_t)(slot * O_STAGE);
        #pragma unroll
        for (int i = 0; i < 12; ++i) {
            int idx = tid + i * 256;
            const void* src;
            uint32_t toff; int local;
            if (i < 4)      { local = idx;        toff = 0;
                              src = Ap  + (size_t)(local >> 3) * K + kc * 64 + (local & 7) * 8; }
            else if (i < 8) { local = idx - 1024; toff = O_BH;
                              src = Bhp + (size_t)(local >> 3) * K + kc * 64 + (local & 7) * 8; }
            else            { local = idx - 2048; toff = O_BL;
                              src = Blp + (size_t)(local >> 3) * K + kc * 64 + (local & 7) * 8; }
            int row = local >> 3, s8 = local & 7;
            cp16(sbase + toff + (uint32_t)(row * 128 + ((s8 * 16) ^ ((row & 7) << 4))), src);
        }
        cp_commit();
    };

    load_stage(0, 0);

    for (int kc = 0; kc < NKC; ++kc) {
        if (kc + 1 < NKC) {
            load_stage((kc + 1) & 1, kc + 1);
            asm volatile("cp.async.wait_group 1;" ::: "memory");
        } else {
            asm volatile("cp.async.wait_group 0;" ::: "memory");
        }
        __syncthreads();

        const uint32_t stg = sb + (uint32_t)((kc & 1) * O_STAGE);

        #pragma unroll
        for (int ks = 0; ks < 4; ++ks) {
            uint32_t aF[2][4];
            const uint32_t colA = (uint32_t)(ks * 32 + acolg) ^ axor;
            const uint32_t colB = (uint32_t)(ks * 32 + bcolg) ^ bxor;
            #pragma unroll
            for (int mf = 0; mf < 2; ++mf)
                ldsm4(aF[mf], stg + (uint32_t)((arow + mf * 16) * 128) + colA);
            #pragma unroll
            for (int nf2 = 0; nf2 < 4; ++nf2) {
                uint32_t bH[4], bL[4];
                const uint32_t ro = (uint32_t)((brow + nf2 * 16) * 128) + colB;
                ldsm4(bH, stg + O_BH + ro);
                ldsm4(bL, stg + O_BL + ro);
                #pragma unroll
                for (int mf = 0; mf < 2; ++mf)
                    #pragma unroll
                    for (int j = 0; j < 2; ++j) {
                        float* c = acc[mf][nf2 * 2 + j];
                        mma16816h(c, aF[mf], &bH[j * 2]);
                        mma16816h(c, aF[mf], &bL[j * 2]);
                    }
            }
        }
        __syncthreads();
    }

    const int row0 = bm + wm * 32 + (lane >> 2);
    const int col0 = bn + wn * 64 + (lane & 3) * 2;
    #pragma unroll
    for (int mf = 0; mf < 2; ++mf)
        #pragma unroll
        for (int nf = 0; nf < 8; ++nf) {
            const int r = row0 + mf * 16;
            const int col = col0 + nf * 8;
            if (QKV) {
                if (wsel == 0) {           // Q: scale, single fp16
                    uint32_t p0 = packh2(acc[mf][nf][0] * QSCALE, acc[mf][nf][1] * QSCALE);
                    uint32_t p1 = packh2(acc[mf][nf][2] * QSCALE, acc[mf][nf][3] * QSCALE);
                    *(uint32_t*)&Q0[(size_t)r * N + col]       = p0;
                    *(uint32_t*)&Q0[(size_t)(r + 8) * N + col] = p1;
                } else {                   // K (wsel 1) / V (wsel 2): fp16 hi/lo
                    __half* Ch = KVh + (size_t)(wsel - 1) * ROWS * EE;
                    __half* Cl = KVl + (size_t)(wsel - 1) * ROWS * EE;
                    uint32_t h0, l0, h1, l1;
                    splitpackh(acc[mf][nf][0], acc[mf][nf][1], h0, l0);
                    splitpackh(acc[mf][nf][2], acc[mf][nf][3], h1, l1);
                    *(uint32_t*)&Ch[(size_t)r * N + col]       = h0;
                    *(uint32_t*)&Cl[(size_t)r * N + col]       = l0;
                    *(uint32_t*)&Ch[(size_t)(r + 8) * N + col] = h1;
                    *(uint32_t*)&Cl[(size_t)(r + 8) * N + col] = l1;
                }
            } else {
                float b0 = bias[col], b1 = bias[col + 1];
                float2 v0, v1;
                v0.x = acc[mf][nf][0] + b0; v0.y = acc[mf][nf][1] + b1;
                v1.x = acc[mf][nf][2] + b0; v1.y = acc[mf][nf][3] + b1;
                *(float2*)&C[(size_t)r * N + col]       = v0;
                *(float2*)&C[(size_t)(r + 8) * N + col] = v1;
            }
        }
}

// ---------------------------------------------------------------------------
// Tensor-core causal flash attention, all-fp16 operands.
// QK^T: Q single fp16 x K fp16 hi/lo (2 terms). PV: P single fp16 x V fp16
// hi/lo (2 terms). Q pre-scaled by 0.125*log2(e) -> exp2 softmax.
// smem: Q[32K] | 3 x (Kh,Kl,Vh,Vl 4x8K) = 128 KB.
// ---------------------------------------------------------------------------
#define FKVB 32768

__global__ __launch_bounds__(512, 1)
void flash_mma(const __half* __restrict__ Q0,
               const __half* __restrict__ Kh, const __half* __restrict__ Kl,
               const __half* __restrict__ Vh, const __half* __restrict__ Vl,
               __half* __restrict__ O)
{
    extern __shared__ char smem[];
    const uint32_t sb = (uint32_t)__cvta_generic_to_shared(smem);
    const int tid = threadIdx.x, w = tid >> 5, lane = tid & 31;
    const int qt = (int)(gridDim.x - 1 - blockIdx.x);   // longest first
    const int bh = blockIdx.y, b = bh >> 4, h = bh & 15;
    const size_t gbase = (size_t)(b * SS) * EE + h * 64;

    const __half* kv[4] = { Kh, Kl, Vh, Vl };

    auto load_kv = [&](int chunk) {
        const uint32_t bufb = sb + 32768 + (uint32_t)((chunk % 3) * FKVB);
        #pragma unroll
        for (int i = 0; i < 4; ++i) {
            int idx = tid + i * 512;
            int t = idx >> 9, rr = (idx & 511) >> 3, s8 = idx & 7;
            cp16(bufb + t * 8192 + rr * 128 + (uint32_t)((s8 * 16) ^ ((rr & 7) << 4)),
                 kv[t] + gbase + (size_t)(chunk * 64 + rr) * EE + s8 * 8);
        }
    };

    // Q tile: 256 rows x 64 fp16 = 32 KB (2048 segs, 4 per thread)
    #pragma unroll
    for (int i = 0; i < 4; ++i) {
        int idx = tid + i * 512;
        int rr = idx >> 3, s8 = idx & 7;
        cp16(sb + rr * 128 + (uint32_t)((s8 * 16) ^ ((rr & 7) << 4)),
             Q0 + gbase + (size_t)(qt * 256 + rr) * EE + s8 * 8);
    }
    load_kv(0);
    cp_commit();
    load_kv(1);
    cp_commit();

    const int r8 = lane & 7, g = lane >> 3;
    const int arow = w * 16 + r8 + (g & 1) * 8;
    const uint32_t axor = (uint32_t)((arow & 7) << 4);
    const int acolg = (g >> 1) * 16;
    const int brow = r8 + (g >> 1) * 8;
    const uint32_t bxor = (uint32_t)((brow & 7) << 4);
    const int bcolg = (g & 1) * 16;
    const int vrow = r8 + (g & 1) * 8;
    const uint32_t vxor = (uint32_t)((vrow & 7) << 4);
    const int vcolg = (g >> 1) * 16;

    float oacc[8][4];
    #pragma unroll
    for (int j = 0; j < 8; ++j)
        #pragma unroll
        for (int e = 0; e < 4; ++e) oacc[j][e] = 0.f;
    float m0 = NEG_INF, m1 = NEG_INF, l0 = 0.f, l1 = 0.f;

    const int nch = 4 * qt + 4;
    const int wminrow = qt * 256 + w * 16;

    for (int c = 0; c < nch; ++c) {
        asm volatile("cp.async.wait_group 1;" ::: "memory");
        __syncthreads();

        if (c + 2 < nch) load_kv(c + 2);
        cp_commit();

        if (c * 64 <= wminrow + 15) {
            const uint32_t bufb = sb + 32768 + (uint32_t)((c % 3) * FKVB);
            float sacc[8][4];
            #pragma unroll
            for (int j = 0; j < 8; ++j)
                #pragma unroll
                for (int e = 0; e < 4; ++e) sacc[j][e] = 0.f;

            // ---- S' = Q' K^T  (Q single fp16, K hi/lo, 2 terms) ----
            #pragma unroll
            for (int ks = 0; ks < 4; ++ks) {
                uint32_t aF[4];
                const uint32_t ao = (uint32_t)(arow * 128) + ((uint32_t)(ks * 32 + acolg) ^ axor);
                ldsm4(aF, sb + ao);
                const uint32_t colB = (uint32_t)(ks * 32 + bcolg) ^ bxor;
                #pragma unroll
                for (int nf2 = 0; nf2 < 4; ++nf2) {
                    uint32_t bH[4], bL[4];
                    const uint32_t ro = (uint32_t)((brow + nf2 * 16) * 128) + colB;
                    ldsm4(bH, bufb + ro);
                    ldsm4(bL, bufb + 8192 + ro);
                    #pragma unroll
                    for (int j = 0; j < 2; ++j) {
                        float* cc = sacc[nf2 * 2 + j];
                        mma16816h(cc, aF, &bH[j * 2]);
                        mma16816h(cc, aF, &bL[j * 2]);
                    }
                }
            }

            // ---- mask + online softmax (base-2) ----
            const int row0 = wminrow + (lane >> 2);
            if (c * 64 + 63 > wminrow) {
                #pragma unroll
                for (int j = 0; j < 8; ++j) {
                    int col = c * 64 + j * 8 + (lane & 3) * 2;
                    if (col     > row0)     sacc[j][0] = NEG_INF;
                    if (col + 1 > row0)     sacc[j][1] = NEG_INF;
                    if (col     > row0 + 8) sacc[j][2] = NEG_INF;
                    if (col + 1 > row0 + 8) sacc[j][3] = NEG_INF;
                }
            }
            float t0 = NEG_INF, t1 = NEG_INF;
            #pragma unroll
            for (int j = 0; j < 8; ++j) {
                t0 = fmaxf(t0, fmaxf(sacc[j][0], sacc[j][1]));
                t1 = fmaxf(t1, fmaxf(sacc[j][2], sacc[j][3]));
            }
            t0 = fmaxf(t0, __shfl_xor_sync(0xffffffffu, t0, 1));
            t0 = fmaxf(t0, __shfl_xor_sync(0xffffffffu, t0, 2));
            t1 = fmaxf(t1, __shfl_xor_sync(0xffffffffu, t1, 1));
            t1 = fmaxf(t1, __shfl_xor_sync(0xffffffffu, t1, 2));

            const float mn0 = fmaxf(m0, t0), mn1 = fmaxf(m1, t1);
            const float cr0 = exp2f(m0 - mn0), cr1 = exp2f(m1 - mn1);
            float s0 = 0.f, s1 = 0.f;
            #pragma unroll
            for (int j = 0; j < 8; ++j) {
                float p0 = exp2f(sacc[j][0] - mn0); sacc[j][0] = p0; s0 += p0;
                float p1 = exp2f(sacc[j][1] - mn0); sacc[j][1] = p1; s0 += p1;
                float p2 = exp2f(sacc[j][2] - mn1); sacc[j][2] = p2; s1 += p2;
                float p3 = exp2f(sacc[j][3] - mn1); sacc[j][3] = p3; s1 += p3;
            }
            s0 += __shfl_xor_sync(0xffffffffu, s0, 1);
            s0 += __shfl_xor_sync(0xffffffffu, s0, 2);
            s1 += __shfl_xor_sync(0xffffffffu, s1, 1);
            s1 += __shfl_xor_sync(0xffffffffu, s1, 2);
            l0 = l0 * cr0 + s0; l1 = l1 * cr1 + s1;
            m0 = mn0; m1 = mn1;
            #pragma unroll
            for (int j = 0; j < 8; ++j) {
                oacc[j][0] *= cr0; oacc[j][1] *= cr0;
                oacc[j][2] *= cr1; oacc[j][3] *= cr1;
            }

            // ---- O += P V  (P single fp16, V hi/lo, 2 terms) ----
            #pragma unroll
            for (int ks = 0; ks < 4; ++ks) {
                uint32_t aP[4];
                aP[0] = packh2(sacc[2*ks][0],   sacc[2*ks][1]);
                aP[1] = packh2(sacc[2*ks][2],   sacc[2*ks][3]);
                aP[2] = packh2(sacc[2*ks+1][0], sacc[2*ks+1][1]);
                aP[3] = packh2(sacc[2*ks+1][2], sacc[2*ks+1][3]);
                const uint32_t rbase = (uint32_t)((ks * 16 + vrow) * 128);
                #pragma unroll
                for (int nf2 = 0; nf2 < 4; ++nf2) {
                    uint32_t vH[4], vL[4];
                    const uint32_t vo = rbase + ((uint32_t)(nf2 * 32 + vcolg) ^ vxor);
                    ldsm4t(vH, bufb + 16384 + vo);
                    ldsm4t(vL, bufb + 24576 + vo);
                    #pragma unroll
                    for (int j = 0; j < 2; ++j) {
                        float* cc = oacc[nf2 * 2 + j];
                        mma16816h(cc, aP, &vH[j * 2]);
                        mma16816h(cc, aP, &vL[j * 2]);
                    }
                }
            }
        }
    }

    const float inv0 = 1.f / l0, inv1 = 1.f / l1;
    const int orow = qt * 256 + w * 16 + (lane >> 2);
    const int ocol = (lane & 3) * 2;
    #pragma unroll
    for (int j = 0; j < 8; ++j) {
        uint32_t p0 = packh2(oacc[j][0] * inv0, oacc[j][1] * inv0);
        uint32_t p1 = packh2(oacc[j][2] * inv1, oacc[j][3] * inv1);
        size_t a0 = gbase + (size_t)orow * EE + j * 8 + ocol;
        size_t a1 = a0 + (size_t)8 * EE;
        *(uint32_t*)&O[a0] = p0;
        *(uint32_t*)&O[a1] = p1;
    }
}

// ---------------------------------------------------------------------------
extern "C" void kernel_launch(void* const* d_in, const int* in_sizes, int n_in,
                              void* d_out, int out_size)
{
    const float* x   = (const float*)d_in[0];
    const float* w_q = (const float*)d_in[2];
    const float* w_k = (const float*)d_in[3];
    const float* w_v = (const float*)d_in[4];
    const float* w_o = (const float*)d_in[5];
    const float* b_o = (const float*)d_in[6];
    float* out = (float*)d_out;

    __half *x16, *q, *kvh, *kvl, *att, *wh, *wl;
    cudaGetSymbolAddress((void**)&x16, g_x16);
    cudaGetSymbolAddress((void**)&q,   g_q);
    cudaGetSymbolAddress((void**)&kvh, g_kvh);
    cudaGetSymbolAddress((void**)&kvl, g_kvl);
    cudaGetSymbolAddress((void**)&att, g_att);
    cudaGetSymbolAddress((void**)&wh,  g_wh);
    cudaGetSymbolAddress((void**)&wl,  g_wl);

    const int nblk = (N4X + 4 * N4W) / 256;
    split_all<<<nblk, 256>>>((const float4*)x,
                             (const float4*)w_q, (const float4*)w_k,
                             (const float4*)w_v, (const float4*)w_o,
                             (uint2*)x16, (uint2*)wh, (uint2*)wl);

    const int osmem = 2 * O_STAGE;       // 98304 -> 2 CTAs/SM
    cudaFuncSetAttribute(mma_gemm<true>,  cudaFuncAttributeMaxDynamicSharedMemorySize, osmem);
    cudaFuncSetAttribute(mma_gemm<false>, cudaFuncAttributeMaxDynamicSharedMemorySize, osmem);

    // QKV: grid (3*8, 64), 2-term fp16
    dim3 gq(3 * EE / 128, ROWS / 128);   // (24, 64)
    mma_gemm<true><<<gq, 256, osmem>>>(x16, wh, wl, nullptr, nullptr,
                                       q, kvh, kvl);

    const size_t TS = (size_t)ROWS * EE;
    const int fsmem = 32768 + 3 * FKVB;  // 131072
    cudaFuncSetAttribute(flash_mma, cudaFuncAttributeMaxDynamicSharedMemorySize, fsmem);
    dim3 fgrid(SS / 256, BB * HH);
    flash_mma<<<fgrid, 512, fsmem>>>(q, kvh, kvl, kvh + TS, kvl + TS, att);

    dim3 gg(EE / 128, ROWS / 128);       // (8, 64)
    mma_gemm<false><<<gg, 256, osmem>>>(att, wh + 3ull*EE*EE, wl + 3ull*EE*EE,
                                        b_o, out, nullptr, nullptr, nullptr);
}

// round 17
// speedup vs baseline: 1.8765x; 1.1224x over previous
#include <cuda_runtime.h>
#include <cuda_bf16.h>
#include <cuda_fp16.h>
#include <math.h>
#include <stdint.h>

#define BB 4
#define SS 2048
#define EE 1024
#define HH 16
#define DD 64
#define ROWS (BB*SS)          // 8192
#define TS ((size_t)ROWS*EE)

#define NEG_INF (__int_as_float(0xff800000))
#define QSCALE 0.18033688011112042f   // 0.125 * log2(e)

// ---------------- scratch (device globals: no runtime allocation) ----------
__device__ __align__(16) __half g_x16[ROWS*EE];          // x, single fp16
__device__ __align__(16) __half g_q[ROWS*EE];            // Q (scaled), fp16
__device__ __align__(16) __half g_kvh[2u*ROWS*EE];       // [K single | V hi]
__device__ __align__(16) __half g_kvl[2u*ROWS*EE];       // [unused   | V lo]
__device__ __align__(16) __half g_att[ROWS*EE];          // attention out, fp16
__device__ __align__(16) __half g_wh[4u*EE*EE];          // weights hi (wq/wk single)
__device__ __align__(16) __half g_wl[4u*EE*EE];          // weights lo (wv/wo only)

#define N4X (ROWS*EE/4)
#define N4W (EE*EE/4)

// ---------------------------------------------------------------------------
// Fused fp32 split: x -> fp16 ; wq,wk -> single fp16 ; wv,wo -> fp16 hi/lo
// ---------------------------------------------------------------------------
__global__ __launch_bounds__(256)
void split_all(const float4* __restrict__ x,
               const float4* __restrict__ w0, const float4* __restrict__ w1,
               const float4* __restrict__ w2, const float4* __restrict__ w3,
               uint2* __restrict__ x16,
               uint2* __restrict__ wh, uint2* __restrict__ wl)
{
    int i = blockIdx.x * 256 + threadIdx.x;
    if (i < N4X) {
        float4 v = x[i];
        uint2 o;
        asm("cvt.rn.f16x2.f32 %0, %1, %2;" : "=r"(o.x) : "f"(v.y), "f"(v.x));
        asm("cvt.rn.f16x2.f32 %0, %1, %2;" : "=r"(o.y) : "f"(v.w), "f"(v.z));
        x16[i] = o;
        return;
    }
    int j = i - N4X;
    int t = j >> 18;
    int loc = j & (N4W - 1);
    const float4* ws[4] = {w0, w1, w2, w3};
    float4 v = ws[t][loc];
    float vv[4] = {v.x, v.y, v.z, v.w};
    unsigned hu[4], lu[4];
    #pragma unroll
    for (int k = 0; k < 4; ++k) {
        __half h = __float2half_rn(vv[k]);
        __half l = __float2half_rn(vv[k] - __half2float(h));
        hu[k] = (unsigned)__half_as_ushort(h);
        lu[k] = (unsigned)__half_as_ushort(l);
    }
    uint2 ho, lv;
    ho.x = hu[0] | (hu[1] << 16); ho.y = hu[2] | (hu[3] << 16);
    lv.x = lu[0] | (lu[1] << 16); lv.y = lu[2] | (lu[3] << 16);
    wh[(size_t)t * N4W + loc] = ho;
    if (t >= 2) wl[(size_t)t * N4W + loc] = lv;   // lo only for wv, wo
}

// ---------------------------------------------------------------------------
// mma.sync helpers
// ---------------------------------------------------------------------------
__device__ __forceinline__ void cp16(uint32_t saddr, const void* gptr) {
    asm volatile("cp.async.cg.shared.global [%0], [%1], 16;"
                 :: "r"(saddr), "l"(gptr));
}
__device__ __forceinline__ void cp_commit() {
    asm volatile("cp.async.commit_group;" ::: "memory");
}
__device__ __forceinline__ void ldsm4(uint32_t* r, uint32_t addr) {
    asm volatile("ldmatrix.sync.aligned.m8n8.x4.shared.b16 {%0,%1,%2,%3}, [%4];"
                 : "=r"(r[0]), "=r"(r[1]), "=r"(r[2]), "=r"(r[3]) : "r"(addr));
}
__device__ __forceinline__ void ldsm4t(uint32_t* r, uint32_t addr) {
    asm volatile("ldmatrix.sync.aligned.m8n8.x4.trans.shared.b16 {%0,%1,%2,%3}, [%4];"
                 : "=r"(r[0]), "=r"(r[1]), "=r"(r[2]), "=r"(r[3]) : "r"(addr));
}
__device__ __forceinline__ void mma16816h(float* c, const uint32_t* a, const uint32_t* b) {
    asm volatile(
        "mma.sync.aligned.m16n8k16.row.col.f32.f16.f16.f32 "
        "{%0,%1,%2,%3}, {%4,%5,%6,%7}, {%8,%9}, {%0,%1,%2,%3};"
        : "+f"(c[0]), "+f"(c[1]), "+f"(c[2]), "+f"(c[3])
        : "r"(a[0]), "r"(a[1]), "r"(a[2]), "r"(a[3]), "r"(b[0]), "r"(b[1]));
}
__device__ __forceinline__ void splitpackh(float a, float b, uint32_t& hi, uint32_t& lo) {
    __half ha = __float2half_rn(a), hb = __float2half_rn(b);
    uint32_t hh = (uint32_t)__half_as_ushort(ha) |
                  ((uint32_t)__half_as_ushort(hb) << 16);
    __half la = __float2half_rn(a - __half2float(ha));
    __half lb = __float2half_rn(b - __half2float(hb));
    uint32_t ll = (uint32_t)__half_as_ushort(la) |
                  ((uint32_t)__half_as_ushort(lb) << 16);
    hi = hh; lo = ll;
}
__device__ __forceinline__ uint32_t packh2(float a, float b) {
    uint32_t r;
    asm("cvt.rn.f16x2.f32 %0, %1, %2;" : "=r"(r) : "f"(b), "f"(a));
    return r;
}

#define NKC (EE/64)

// ===========================================================================
// fp16 GEMM core: CTA 128x128, 8 warps (4x2), warp tile 32x64,
// 2-stage x 48KB = 96KB => 2 CTAs/SM.
// QKV=true : A = x fp16; wsel 0/1 (Q/K): 1-term (W single fp16);
//            wsel 2 (V): 2-term hi/lo. Epilogue: Q scaled fp16, K fp16,
//            V fp16 hi/lo.
// QKV=false: O-projection, always 2-term; fp32 + bias epilogue.
// ===========================================================================
#define O_BH 16384
#define O_BL 32768
#define O_STAGE 49152

template<bool QKV>
__global__ __launch_bounds__(256, 2)
void mma_gemm(const __half* __restrict__ A0,
              const __half* __restrict__ Wh0, const __half* __restrict__ Wl0,
              const float* __restrict__ bias, float* __restrict__ C,
              __half* __restrict__ Q0,
              __half* __restrict__ KVh, __half* __restrict__ KVl)
{
    extern __shared__ char smem[];
    const uint32_t sb = (uint32_t)__cvta_generic_to_shared(smem);
    const int K = EE, N = EE;

    const int tid = threadIdx.x;
    const int w = tid >> 5, lane = tid & 31;
    const int wm = w & 3, wn = w >> 2;               // 4x2: warp tile 32x64
    const int wsel = QKV ? (blockIdx.x >> 3) : 0;
    const int bm = blockIdx.y * 128;
    const int bn = QKV ? ((blockIdx.x & 7) * 128) : (blockIdx.x * 128);
    const bool two_term = !QKV || (wsel == 2);

    const __half* Ap  = A0 + (size_t)bm * K;
    const __half* Bhp = Wh0 + (size_t)wsel * EE * EE + (size_t)bn * K;
    const __half* Blp = Wl0 + (size_t)wsel * EE * EE + (size_t)bn * K;

    const int r8 = lane & 7, g = lane >> 3;
    const int arow = wm * 32 + r8 + (g & 1) * 8;
    const int acolg = (g >> 1) * 16;
    const uint32_t axor = (uint32_t)((arow & 7) << 4);
    const int brow = wn * 64 + r8 + (g >> 1) * 8;
    const int bcolg = (g & 1) * 16;
    const uint32_t bxor = (uint32_t)((brow & 7) << 4);

    float acc[2][8][4];
    #pragma unroll
    for (int a = 0; a < 2; ++a)
        #pragma unroll
        for (int b = 0; b < 8; ++b)
            #pragma unroll
            for (int c = 0; c < 4; ++c) acc[a][b][c] = 0.f;

    auto load_stage = [&](int slot, int kc) {
        const uint32_t sbase = sb + (uint32_t)(slot * O_STAGE);
        #pragma unroll
        for (int i = 0; i < 12; ++i) {
            if (i >= 8 && !two_term) break;       // skip Bl for 1-term CTAs
            int idx = tid + i * 256;
            const void* src;
            uint32_t toff; int local;
            if (i < 4)      { local = idx;        toff = 0;
                              src = Ap  + (size_t)(local >> 3) * K + kc * 64 + (local & 7) * 8; }
            else if (i < 8) { local = idx - 1024; toff = O_BH;
                              src = Bhp + (size_t)(local >> 3) * K + kc * 64 + (local & 7) * 8; }
            else            { local = idx - 2048; toff = O_BL;
                              src = Blp + (size_t)(local >> 3) * K + kc * 64 + (local & 7) * 8; }
            int row = local >> 3, s8 = local & 7;
            cp16(sbase + toff + (uint32_t)(row * 128 + ((s8 * 16) ^ ((row & 7) << 4))), src);
        }
        cp_commit();
    };

    load_stage(0, 0);

    for (int kc = 0; kc < NKC; ++kc) {
        if (kc + 1 < NKC) {
            load_stage((kc + 1) & 1, kc + 1);
            asm volatile("cp.async.wait_group 1;" ::: "memory");
        } else {
            asm volatile("cp.async.wait_group 0;" ::: "memory");
        }
        __syncthreads();

        const uint32_t stg = sb + (uint32_t)((kc & 1) * O_STAGE);

        #pragma unroll
        for (int ks = 0; ks < 4; ++ks) {
            uint32_t aF[2][4];
            const uint32_t colA = (uint32_t)(ks * 32 + acolg) ^ axor;
            const uint32_t colB = (uint32_t)(ks * 32 + bcolg) ^ bxor;
            #pragma unroll
            for (int mf = 0; mf < 2; ++mf)
                ldsm4(aF[mf], stg + (uint32_t)((arow + mf * 16) * 128) + colA);
            #pragma unroll
            for (int nf2 = 0; nf2 < 4; ++nf2) {
                uint32_t bH[4], bL[4];
                const uint32_t ro = (uint32_t)((brow + nf2 * 16) * 128) + colB;
                ldsm4(bH, stg + O_BH + ro);
                if (two_term) ldsm4(bL, stg + O_BL + ro);
                #pragma unroll
                for (int mf = 0; mf < 2; ++mf)
                    #pragma unroll
                    for (int j = 0; j < 2; ++j) {
                        float* c = acc[mf][nf2 * 2 + j];
                        mma16816h(c, aF[mf], &bH[j * 2]);
                        if (two_term) mma16816h(c, aF[mf], &bL[j * 2]);
                    }
            }
        }
        __syncthreads();
    }

    const int row0 = bm + wm * 32 + (lane >> 2);
    const int col0 = bn + wn * 64 + (lane & 3) * 2;
    #pragma unroll
    for (int mf = 0; mf < 2; ++mf)
        #pragma unroll
        for (int nf = 0; nf < 8; ++nf) {
            const int r = row0 + mf * 16;
            const int col = col0 + nf * 8;
            if (QKV) {
                if (wsel == 0) {           // Q: scale, single fp16
                    uint32_t p0 = packh2(acc[mf][nf][0] * QSCALE, acc[mf][nf][1] * QSCALE);
                    uint32_t p1 = packh2(acc[mf][nf][2] * QSCALE, acc[mf][nf][3] * QSCALE);
                    *(uint32_t*)&Q0[(size_t)r * N + col]       = p0;
                    *(uint32_t*)&Q0[(size_t)(r + 8) * N + col] = p1;
                } else if (wsel == 1) {    // K: single fp16 (slice 0 of KVh)
                    uint32_t p0 = packh2(acc[mf][nf][0], acc[mf][nf][1]);
                    uint32_t p1 = packh2(acc[mf][nf][2], acc[mf][nf][3]);
                    *(uint32_t*)&KVh[(size_t)r * N + col]       = p0;
                    *(uint32_t*)&KVh[(size_t)(r + 8) * N + col] = p1;
                } else {                   // V: fp16 hi/lo (slice 1)
                    __half* Ch = KVh + TS;
                    __half* Cl = KVl + TS;
                    uint32_t h0, l0, h1, l1;
                    splitpackh(acc[mf][nf][0], acc[mf][nf][1], h0, l0);
                    splitpackh(acc[mf][nf][2], acc[mf][nf][3], h1, l1);
                    *(uint32_t*)&Ch[(size_t)r * N + col]       = h0;
                    *(uint32_t*)&Cl[(size_t)r * N + col]       = l0;
                    *(uint32_t*)&Ch[(size_t)(r + 8) * N + col] = h1;
                    *(uint32_t*)&Cl[(size_t)(r + 8) * N + col] = l1;
                }
            } else {
                float b0 = bias[col], b1 = bias[col + 1];
                float2 v0, v1;
                v0.x = acc[mf][nf][0] + b0; v0.y = acc[mf][nf][1] + b1;
                v1.x = acc[mf][nf][2] + b0; v1.y = acc[mf][nf][3] + b1;
                *(float2*)&C[(size_t)r * N + col]       = v0;
                *(float2*)&C[(size_t)(r + 8) * N + col] = v1;
            }
        }
}

// ---------------------------------------------------------------------------
// Tensor-core causal flash attention, all-fp16 operands.
// QK^T: Q fp16 x K fp16 (1 term). PV: P fp16 x V fp16 hi/lo (2 terms).
// Q pre-scaled by 0.125*log2(e) -> exp2 softmax.
// smem: Q[32K] | 3 x (K,Vh,Vl 3x8K = 24K) = 104 KB.
// ---------------------------------------------------------------------------
#define FKVB 24576

__global__ __launch_bounds__(512, 1)
void flash_mma(const __half* __restrict__ Q0,
               const __half* __restrict__ K0,
               const __half* __restrict__ Vh, const __half* __restrict__ Vl,
               __half* __restrict__ O)
{
    extern __shared__ char smem[];
    const uint32_t sb = (uint32_t)__cvta_generic_to_shared(smem);
    const int tid = threadIdx.x, w = tid >> 5, lane = tid & 31;
    const int qt = (int)(gridDim.x - 1 - blockIdx.x);   // longest first
    const int bh = blockIdx.y, b = bh >> 4, h = bh & 15;
    const size_t gbase = (size_t)(b * SS) * EE + h * 64;

    const __half* kv[3] = { K0, Vh, Vl };

    auto load_kv = [&](int chunk) {
        const uint32_t bufb = sb + 32768 + (uint32_t)((chunk % 3) * FKVB);
        #pragma unroll
        for (int i = 0; i < 3; ++i) {
            int idx = tid + i * 512;
            int t = idx >> 9, rr = (idx & 511) >> 3, s8 = idx & 7;
            cp16(bufb + t * 8192 + rr * 128 + (uint32_t)((s8 * 16) ^ ((rr & 7) << 4)),
                 kv[t] + gbase + (size_t)(chunk * 64 + rr) * EE + s8 * 8);
        }
    };

    // Q tile: 256 rows x 64 fp16 = 32 KB
    #pragma unroll
    for (int i = 0; i < 4; ++i) {
        int idx = tid + i * 512;
        int rr = idx >> 3, s8 = idx & 7;
        cp16(sb + rr * 128 + (uint32_t)((s8 * 16) ^ ((rr & 7) << 4)),
             Q0 + gbase + (size_t)(qt * 256 + rr) * EE + s8 * 8);
    }
    load_kv(0);
    cp_commit();
    load_kv(1);
    cp_commit();

    const int r8 = lane & 7, g = lane >> 3;
    const int arow = w * 16 + r8 + (g & 1) * 8;
    const uint32_t axor = (uint32_t)((arow & 7) << 4);
    const int acolg = (g >> 1) * 16;
    const int brow = r8 + (g >> 1) * 8;
    const uint32_t bxor = (uint32_t)((brow & 7) << 4);
    const int bcolg = (g & 1) * 16;
    const int vrow = r8 + (g & 1) * 8;
    const uint32_t vxor = (uint32_t)((vrow & 7) << 4);
    const int vcolg = (g >> 1) * 16;

    float oacc[8][4];
    #pragma unroll
    for (int j = 0; j < 8; ++j)
        #pragma unroll
        for (int e = 0; e < 4; ++e) oacc[j][e] = 0.f;
    float m0 = NEG_INF, m1 = NEG_INF, l0 = 0.f, l1 = 0.f;

    const int nch = 4 * qt + 4;
    const int wminrow = qt * 256 + w * 16;

    for (int c = 0; c < nch; ++c) {
        asm volatile("cp.async.wait_group 1;" ::: "memory");
        __syncthreads();

        if (c + 2 < nch) load_kv(c + 2);
        cp_commit();

        if (c * 64 <= wminrow + 15) {
            const uint32_t bufb = sb + 32768 + (uint32_t)((c % 3) * FKVB);
            float sacc[8][4];
            #pragma unroll
            for (int j = 0; j < 8; ++j)
                #pragma unroll
                for (int e = 0; e < 4; ++e) sacc[j][e] = 0.f;

            // ---- S' = Q' K^T  (1 term) ----
            #pragma unroll
            for (int ks = 0; ks < 4; ++ks) {
                uint32_t aF[4];
                const uint32_t ao = (uint32_t)(arow * 128) + ((uint32_t)(ks * 32 + acolg) ^ axor);
                ldsm4(aF, sb + ao);
                const uint32_t colB = (uint32_t)(ks * 32 + bcolg) ^ bxor;
                #pragma unroll
                for (int nf2 = 0; nf2 < 4; ++nf2) {
                    uint32_t bK[4];
                    ldsm4(bK, bufb + (uint32_t)((brow + nf2 * 16) * 128) + colB);
                    #pragma unroll
                    for (int j = 0; j < 2; ++j)
                        mma16816h(sacc[nf2 * 2 + j], aF, &bK[j * 2]);
                }
            }

            // ---- mask + online softmax (base-2) ----
            const int row0 = wminrow + (lane >> 2);
            if (c * 64 + 63 > wminrow) {
                #pragma unroll
                for (int j = 0; j < 8; ++j) {
                    int col = c * 64 + j * 8 + (lane & 3) * 2;
                    if (col     > row0)     sacc[j][0] = NEG_INF;
                    if (col + 1 > row0)     sacc[j][1] = NEG_INF;
                    if (col     > row0 + 8) sacc[j][2] = NEG_INF;
                    if (col + 1 > row0 + 8) sacc[j][3] = NEG_INF;
                }
            }
            float t0 = NEG_INF, t1 = NEG_INF;
            #pragma unroll
            for (int j = 0; j < 8; ++j) {
                t0 = fmaxf(t0, fmaxf(sacc[j][0], sacc[j][1]));
                t1 = fmaxf(t1, fmaxf(sacc[j][2], sacc[j][3]));
            }
            t0 = fmaxf(t0, __shfl_xor_sync(0xffffffffu, t0, 1));
            t0 = fmaxf(t0, __shfl_xor_sync(0xffffffffu, t0, 2));
            t1 = fmaxf(t1, __shfl_xor_sync(0xffffffffu, t1, 1));
            t1 = fmaxf(t1, __shfl_xor_sync(0xffffffffu, t1, 2));

            const float mn0 = fmaxf(m0, t0), mn1 = fmaxf(m1, t1);
            const float cr0 = exp2f(m0 - mn0), cr1 = exp2f(m1 - mn1);
            float s0 = 0.f, s1 = 0.f;
            #pragma unroll
            for (int j = 0; j < 8; ++j) {
                float p0 = exp2f(sacc[j][0] - mn0); sacc[j][0] = p0; s0 += p0;
                float p1 = exp2f(sacc[j][1] - mn0); sacc[j][1] = p1; s0 += p1;
                float p2 = exp2f(sacc[j][2] - mn1); sacc[j][2] = p2; s1 += p2;
                float p3 = exp2f(sacc[j][3] - mn1); sacc[j][3] = p3; s1 += p3;
            }
            s0 += __shfl_xor_sync(0xffffffffu, s0, 1);
            s0 += __shfl_xor_sync(0xffffffffu, s0, 2);
            s1 += __shfl_xor_sync(0xffffffffu, s1, 1);
            s1 += __shfl_xor_sync(0xffffffffu, s1, 2);
            l0 = l0 * cr0 + s0; l1 = l1 * cr1 + s1;
            m0 = mn0; m1 = mn1;
            #pragma unroll
            for (int j = 0; j < 8; ++j) {
                oacc[j][0] *= cr0; oacc[j][1] *= cr0;
                oacc[j][2] *= cr1; oacc[j][3] *= cr1;
            }

            // ---- O += P V  (P fp16, V hi/lo, 2 terms) ----
            #pragma unroll
            for (int ks = 0; ks < 4; ++ks) {
                uint32_t aP[4];
                aP[0] = packh2(sacc[2*ks][0],   sacc[2*ks][1]);
                aP[1] = packh2(sacc[2*ks][2],   sacc[2*ks][3]);
                aP[2] = packh2(sacc[2*ks+1][0], sacc[2*ks+1][1]);
                aP[3] = packh2(sacc[2*ks+1][2], sacc[2*ks+1][3]);
                const uint32_t rbase = (uint32_t)((ks * 16 + vrow) * 128);
                #pragma unroll
                for (int nf2 = 0; nf2 < 4; ++nf2) {
                    uint32_t vH[4], vL[4];
                    const uint32_t vo = rbase + ((uint32_t)(nf2 * 32 + vcolg) ^ vxor);
                    ldsm4t(vH, bufb + 8192  + vo);
                    ldsm4t(vL, bufb + 16384 + vo);
                    #pragma unroll
                    for (int j = 0; j < 2; ++j) {
                        float* cc = oacc[nf2 * 2 + j];
                        mma16816h(cc, aP, &vH[j * 2]);
                        mma16816h(cc, aP, &vL[j * 2]);
                    }
                }
            }
        }
    }

    const float inv0 = 1.f / l0, inv1 = 1.f / l1;
    const int orow = qt * 256 + w * 16 + (lane >> 2);
    const int ocol = (lane & 3) * 2;
    #pragma unroll
    for (int j = 0; j < 8; ++j) {
        uint32_t p0 = packh2(oacc[j][0] * inv0, oacc[j][1] * inv0);
        uint32_t p1 = packh2(oacc[j][2] * inv1, oacc[j][3] * inv1);
        size_t a0 = gbase + (size_t)orow * EE + j * 8 + ocol;
        size_t a1 = a0 + (size_t)8 * EE;
        *(uint32_t*)&O[a0] = p0;
        *(uint32_t*)&O[a1] = p1;
    }
}

// ---------------------------------------------------------------------------
extern "C" void kernel_launch(void* const* d_in, const int* in_sizes, int n_in,
                              void* d_out, int out_size)
{
    const float* x   = (const float*)d_in[0];
    const float* w_q = (const float*)d_in[2];
    const float* w_k = (const float*)d_in[3];
    const float* w_v = (const float*)d_in[4];
    const float* w_o = (const float*)d_in[5];
    const float* b_o = (const float*)d_in[6];
    float* out = (float*)d_out;

    __half *x16, *q, *kvh, *kvl, *att, *wh, *wl;
    cudaGetSymbolAddress((void**)&x16, g_x16);
    cudaGetSymbolAddress((void**)&q,   g_q);
    cudaGetSymbolAddress((void**)&kvh, g_kvh);
    cudaGetSymbolAddress((void**)&kvl, g_kvl);
    cudaGetSymbolAddress((void**)&att, g_att);
    cudaGetSymbolAddress((void**)&wh,  g_wh);
    cudaGetSymbolAddress((void**)&wl,  g_wl);

    const int nblk = (N4X + 4 * N4W) / 256;
    split_all<<<nblk, 256>>>((const float4*)x,
                             (const float4*)w_q, (const float4*)w_k,
                             (const float4*)w_v, (const float4*)w_o,
                             (uint2*)x16, (uint2*)wh, (uint2*)wl);

    const int osmem = 2 * O_STAGE;       // 98304 -> 2 CTAs/SM
    cudaFuncSetAttribute(mma_gemm<true>,  cudaFuncAttributeMaxDynamicSharedMemorySize, osmem);
    cudaFuncSetAttribute(mma_gemm<false>, cudaFuncAttributeMaxDynamicSharedMemorySize, osmem);

    // QKV: grid (3*8, 64); Q/K 1-term, V 2-term
    dim3 gq(3 * EE / 128, ROWS / 128);   // (24, 64)
    mma_gemm<true><<<gq, 256, osmem>>>(x16, wh, wl, nullptr, nullptr,
                                       q, kvh, kvl);

    const int fsmem = 32768 + 3 * FKVB;  // 106496
    cudaFuncSetAttribute(flash_mma, cudaFuncAttributeMaxDynamicSharedMemorySize, fsmem);
    dim3 fgrid(SS / 256, BB * HH);
    flash_mma<<<fgrid, 512, fsmem>>>(q, kvh, kvh + TS, kvl + TS, att);

    dim3 gg(EE / 128, ROWS / 128);       // (8, 64)
    mma_gemm<false><<<gg, 256, osmem>>>(att, wh + 3ull*EE*EE, wl + 3ull*EE*EE,
                                        b_o, out, nullptr, nullptr, nullptr);
}